// round 4
// baseline (speedup 1.0000x reference)
#include <cuda_runtime.h>
#include <cuda_bf16.h>
#include <math.h>
#include <stdint.h>

#define SQ   2048
#define DM   1024
#define NH   16
#define HDIM 64
#define MLPD 4096
#define NL   4
#define HALFW 256
#define NG   64

// ---------------- scratch (device globals; no allocation allowed) ----------
__device__ float g_x[SQ * DM];
__device__ float g_h[SQ * DM];
__device__ float g_q[SQ * DM];
__device__ float g_k[SQ * DM];
__device__ float g_v[SQ * DM];
__device__ float g_ctx[SQ * DM];
__device__ float g_y1[SQ * MLPD];
__device__ float g_wqT[NL * DM * DM];
__device__ float g_wkT[NL * DM * DM];
__device__ float g_wvT[NL * DM * DM];
__device__ float g_woT[NL * DM * DM];
__device__ float g_w1T[NL * DM * MLPD];
__device__ float g_w2T[NL * MLPD * DM];

// ---------------- helpers ---------------------------------------------------
__device__ __forceinline__ uint32_t smem_u32(const void* p) {
    uint32_t a;
    asm("{ .reg .u64 t; cvta.to.shared.u64 t, %1; cvt.u32.u64 %0, t; }"
        : "=r"(a) : "l"(p));
    return a;
}

__device__ __forceinline__ void ldsm4(uint32_t* r, uint32_t addr) {
    asm volatile("ldmatrix.sync.aligned.m8n8.x4.shared.b16 {%0,%1,%2,%3}, [%4];"
                 : "=r"(r[0]), "=r"(r[1]), "=r"(r[2]), "=r"(r[3]) : "r"(addr));
}

__device__ __forceinline__ void mma_bf16(float* c, const uint32_t* a,
                                         const uint32_t* b) {
    asm volatile(
        "mma.sync.aligned.m16n8k16.row.col.f32.bf16.bf16.f32 "
        "{%0,%1,%2,%3}, {%4,%5,%6,%7}, {%8,%9}, {%0,%1,%2,%3};"
        : "+f"(c[0]), "+f"(c[1]), "+f"(c[2]), "+f"(c[3])
        : "r"(a[0]), "r"(a[1]), "r"(a[2]), "r"(a[3]), "r"(b[0]), "r"(b[1]));
}

// smem geometry (bytes)
#define ROWB  80            // 32 bf16 = 64B data + 16B pad (5 x 16B -> conflict-free)
#define PART  (128 * ROWB)  // one operand-part tile: 10240 B
#define BUFB  (4 * PART)    // Ah, Al, Bh, Bl
#define DYNSM (2 * BUFB)    // double buffer: 81920 B

// ---------------------------------------------------------------------------
// bf16-split tensor-core GEMM: C[M,N] = epi(alpha * A[M,K] @ BT[N,K]^T)
// A fp32 [M,K] row-major, BT fp32 [N,K] row-major.
// 128x128x32 tile, 256 thr, warp tile 64x32, m16n8k16 mma.sync,
// 3-term bf16 split (hi*hi + hi*lo + lo*hi).
// ---------------------------------------------------------------------------
template <int BIAS, int RELU, int RESID>
__global__ __launch_bounds__(256) void mma_gemm(
    const float* __restrict__ A, const float* __restrict__ BT,
    const float* __restrict__ bias, const float* __restrict__ resid,
    float* __restrict__ C, int K, int N, float alpha) {
    extern __shared__ __align__(16) char dsm[];
    const uint32_t sbase = smem_u32(dsm);

    const int tid = threadIdx.x;
    const int wid = tid >> 5, lane = tid & 31;
    const int srow = tid >> 1, shalf = tid & 1;
    const uint32_t rowoff = (uint32_t)(srow * ROWB + shalf * 32);

    const float* Ap = A + ((size_t)blockIdx.y * 128 + srow) * (size_t)K + shalf * 16;
    const float* Bp = BT + ((size_t)blockIdx.x * 128 + srow) * (size_t)K + shalf * 16;

    float acc[4][4][4];
#pragma unroll
    for (int i = 0; i < 4; i++)
#pragma unroll
        for (int j = 0; j < 4; j++)
#pragma unroll
            for (int f = 0; f < 4; f++) acc[i][j][f] = 0.0f;

    float ra[16], rb[16];

#define LDG16(dst, ptr)                                          \
    {                                                            \
        *(float4*)((dst) + 0)  = *(const float4*)((ptr) + 0);    \
        *(float4*)((dst) + 4)  = *(const float4*)((ptr) + 4);    \
        *(float4*)((dst) + 8)  = *(const float4*)((ptr) + 8);    \
        *(float4*)((dst) + 12) = *(const float4*)((ptr) + 12);   \
    }

#define CVT_STS(hibase, lobase, r)                                               \
    {                                                                            \
        uint32_t hw[8], lw[8];                                                   \
        _Pragma("unroll") for (int i = 0; i < 8; i++) {                          \
            float f0 = (r)[2 * i], f1 = (r)[2 * i + 1];                          \
            __nv_bfloat16 h0 = __float2bfloat16_rn(f0);                          \
            __nv_bfloat16 h1 = __float2bfloat16_rn(f1);                          \
            __nv_bfloat16 l0 = __float2bfloat16_rn(f0 - __bfloat162float(h0));   \
            __nv_bfloat16 l1 = __float2bfloat16_rn(f1 - __bfloat162float(h1));   \
            hw[i] = ((uint32_t)__bfloat16_as_ushort(h1) << 16) |                 \
                    __bfloat16_as_ushort(h0);                                    \
            lw[i] = ((uint32_t)__bfloat16_as_ushort(l1) << 16) |                 \
                    __bfloat16_as_ushort(l0);                                    \
        }                                                                        \
        asm volatile("st.shared.v4.b32 [%0], {%1,%2,%3,%4};" ::"r"(hibase),      \
                     "r"(hw[0]), "r"(hw[1]), "r"(hw[2]), "r"(hw[3]) : "memory"); \
        asm volatile("st.shared.v4.b32 [%0], {%1,%2,%3,%4};" ::"r"(hibase + 16), \
                     "r"(hw[4]), "r"(hw[5]), "r"(hw[6]), "r"(hw[7]) : "memory"); \
        asm volatile("st.shared.v4.b32 [%0], {%1,%2,%3,%4};" ::"r"(lobase),      \
                     "r"(lw[0]), "r"(lw[1]), "r"(lw[2]), "r"(lw[3]) : "memory"); \
        asm volatile("st.shared.v4.b32 [%0], {%1,%2,%3,%4};" ::"r"(lobase + 16), \
                     "r"(lw[4]), "r"(lw[5]), "r"(lw[6]), "r"(lw[7]) : "memory"); \
    }

    const int CH = K >> 5;

    // prologue: stage chunk 0
    LDG16(ra, Ap);
    LDG16(rb, Bp);
    {
        uint32_t b0 = sbase + rowoff;
        CVT_STS(b0, b0 + PART, ra);
        uint32_t b2 = b0 + 2 * PART;
        CVT_STS(b2, b2 + PART, rb);
    }
    __syncthreads();

    const int m_base = (wid & 1) * 64;
    const int n_base = (wid >> 1) * 32;
    const int lgrp = lane >> 3, lr = lane & 7;

    for (int c = 0; c < CH; c++) {
        if (c + 1 < CH) {
            LDG16(ra, Ap + (size_t)(c + 1) * 32);
            LDG16(rb, Bp + (size_t)(c + 1) * 32);
        }
        const uint32_t sb0 = sbase + (uint32_t)(c & 1) * BUFB;
#pragma unroll
        for (int ks = 0; ks < 2; ks++) {
            uint32_t bh[4][2], bl[4][2];
#pragma unroll
            for (int p = 0; p < 2; p++) {
                uint32_t row = (uint32_t)(n_base + p * 16 + (lgrp >> 1) * 8 + lr);
                uint32_t ad = sb0 + 2 * PART + row * ROWB + ks * 32 + (lgrp & 1) * 16;
                uint32_t t[4];
                ldsm4(t, ad);
                bh[2 * p][0] = t[0]; bh[2 * p][1] = t[1];
                bh[2 * p + 1][0] = t[2]; bh[2 * p + 1][1] = t[3];
                ldsm4(t, ad + PART);
                bl[2 * p][0] = t[0]; bl[2 * p][1] = t[1];
                bl[2 * p + 1][0] = t[2]; bl[2 * p + 1][1] = t[3];
            }
#pragma unroll
            for (int mt = 0; mt < 4; mt++) {
                uint32_t row = (uint32_t)(m_base + mt * 16 + (lgrp & 1) * 8 + lr);
                uint32_t ad = sb0 + row * ROWB + ks * 32 + (lgrp >> 1) * 16;
                uint32_t ah[4], al[4];
                ldsm4(ah, ad);
                ldsm4(al, ad + PART);
#pragma unroll
                for (int nt = 0; nt < 4; nt++) {
                    mma_bf16(acc[mt][nt], ah, bh[nt]);
                    mma_bf16(acc[mt][nt], ah, bl[nt]);
                    mma_bf16(acc[mt][nt], al, bh[nt]);
                }
            }
        }
        if (c + 1 < CH) {
            uint32_t b0 = sbase + (uint32_t)((c + 1) & 1) * BUFB + rowoff;
            CVT_STS(b0, b0 + PART, ra);
            uint32_t b2 = b0 + 2 * PART;
            CVT_STS(b2, b2 + PART, rb);
        }
        __syncthreads();
    }

    // epilogue
    const int m0 = blockIdx.y * 128 + m_base;
    const int n0 = blockIdx.x * 128 + n_base;
    const int mr = lane >> 2, nc = (lane & 3) * 2;
#pragma unroll
    for (int mt = 0; mt < 4; mt++) {
#pragma unroll
        for (int half = 0; half < 2; half++) {
            const size_t m = (size_t)(m0 + mt * 16 + mr + half * 8);
#pragma unroll
            for (int nt = 0; nt < 4; nt++) {
                const int n = n0 + nt * 8 + nc;
                float v0 = acc[mt][nt][2 * half] * alpha;
                float v1 = acc[mt][nt][2 * half + 1] * alpha;
                if (BIAS) { v0 += bias[n]; v1 += bias[n + 1]; }
                if (RELU) { v0 = fmaxf(v0, 0.0f); v1 = fmaxf(v1, 0.0f); }
                if (RESID) {
                    float2 r2 = *(const float2*)(resid + m * N + n);
                    v0 += r2.x; v1 += r2.y;
                }
                float2 o; o.x = v0; o.y = v1;
                *(float2*)(C + m * N + n) = o;
            }
        }
    }
}

// ---------------------------------------------------------------------------
// Weight transpose: in [R,C] -> out [C,R], batched over blockIdx.z
// ---------------------------------------------------------------------------
__global__ void transpose_kernel(const float* __restrict__ in,
                                 float* __restrict__ out, int R, int C) {
    __shared__ float t[32][33];
    const size_t boff = (size_t)blockIdx.z * R * C;
    const int c0 = blockIdx.x * 32, r0 = blockIdx.y * 32;
    for (int k = threadIdx.y; k < 32; k += 8)
        t[k][threadIdx.x] = in[boff + (size_t)(r0 + k) * C + c0 + threadIdx.x];
    __syncthreads();
    for (int k = threadIdx.y; k < 32; k += 8)
        out[boff + (size_t)(c0 + k) * R + r0 + threadIdx.x] = t[threadIdx.x][k];
}

// ---------------------------------------------------------------------------
// Embedding + sinusoidal positional encoding
// ---------------------------------------------------------------------------
__global__ void embed_kernel(const int* __restrict__ inputs,
                             const float* __restrict__ emb) {
    int idx = blockIdx.x * blockDim.x + threadIdx.x;
    int s = idx >> 10;
    int d = idx & 1023;
    int tok = inputs[s];
    float val = emb[tok * DM + d];
    int k2 = d >> 1;
    float div = expf((float)(2 * k2) * (-9.210340371976184f / 1024.0f));
    float ang = (float)s * div;
    val += (d & 1) ? cosf(ang) : sinf(ang);
    g_x[idx] = val;
}

// ---------------------------------------------------------------------------
// LayerNorm
// ---------------------------------------------------------------------------
__device__ __forceinline__ float block_reduce_sum(float v) {
    __shared__ float sm[8];
    int lane = threadIdx.x & 31;
    int warp = threadIdx.x >> 5;
#pragma unroll
    for (int o = 16; o; o >>= 1) v += __shfl_xor_sync(0xffffffffu, v, o);
    if (lane == 0) sm[warp] = v;
    __syncthreads();
    if (warp == 0) {
        v = (lane < 8) ? sm[lane] : 0.0f;
#pragma unroll
        for (int o = 4; o; o >>= 1) v += __shfl_xor_sync(0xffffffffu, v, o);
        if (lane == 0) sm[0] = v;
    }
    __syncthreads();
    float r = sm[0];
    __syncthreads();
    return r;
}

__global__ void ln_kernel(const float* __restrict__ in,
                          const float* __restrict__ scale,
                          const float* __restrict__ bias,
                          float* __restrict__ out) {
    int row = blockIdx.x;
    float4 v = ((const float4*)(in + row * DM))[threadIdx.x];
    float mu = block_reduce_sum(v.x + v.y + v.z + v.w) * (1.0f / DM);
    float dx = v.x - mu, dy = v.y - mu, dz = v.z - mu, dw = v.w - mu;
    float var = block_reduce_sum(dx * dx + dy * dy + dz * dz + dw * dw) * (1.0f / DM);
    float rs = rsqrtf(var + 1e-6f);
    float4 s4 = ((const float4*)scale)[threadIdx.x];
    float4 b4 = ((const float4*)bias)[threadIdx.x];
    float4 o;
    o.x = dx * rs * s4.x + b4.x;
    o.y = dy * rs * s4.y + b4.y;
    o.z = dz * rs * s4.z + b4.z;
    o.w = dw * rs * s4.w + b4.w;
    ((float4*)(out + row * DM))[threadIdx.x] = o;
}

// ---------------------------------------------------------------------------
// Sparse attention (band + global), one block per (query, head)
// ---------------------------------------------------------------------------
__global__ __launch_bounds__(128) void attn_kernel() {
    int i = blockIdx.x;
    int head = blockIdx.y;
    __shared__ float qs[HDIM];
    __shared__ float sc[SQ];
    __shared__ float red[128];
    int tid = threadIdx.x;

    if (tid < HDIM) qs[tid] = g_q[(size_t)i * DM + head * HDIM + tid];
    __syncthreads();

    int n0, r1lo, r1hi;
    if (i < NG) {
        n0 = SQ; r1lo = 0; r1hi = 0;
    } else {
        n0 = NG;
        r1lo = max(NG, i - HALFW);
        r1hi = min(SQ, i + HALFW + 1);
    }
    int n = n0 + (r1hi - r1lo);

    int warp = tid >> 5, lane = tid & 31;
    for (int t = warp; t < n; t += 4) {
        int j = (t < n0) ? t : (r1lo + (t - n0));
        const float* kr = g_k + (size_t)j * DM + head * HDIM;
        float2 kk = ((const float2*)kr)[lane];
        float p = qs[2 * lane] * kk.x + qs[2 * lane + 1] * kk.y;
#pragma unroll
        for (int o = 16; o; o >>= 1) p += __shfl_xor_sync(0xffffffffu, p, o);
        if (lane == 0) sc[t] = p;
    }
    __syncthreads();

    float mx = -1e30f;
    for (int t = tid; t < n; t += 128) mx = fmaxf(mx, sc[t]);
    red[tid] = mx;
    __syncthreads();
    for (int s2 = 64; s2 > 0; s2 >>= 1) {
        if (tid < s2) red[tid] = fmaxf(red[tid], red[tid + s2]);
        __syncthreads();
    }
    mx = red[0];
    __syncthreads();

    float lsum = 0.0f;
    for (int t = tid; t < n; t += 128) {
        float e = expf(sc[t] - mx);
        sc[t] = e;
        lsum += e;
    }
    red[tid] = lsum;
    __syncthreads();
    for (int s2 = 64; s2 > 0; s2 >>= 1) {
        if (tid < s2) red[tid] += red[tid + s2];
        __syncthreads();
    }
    float denom = red[0];
    __syncthreads();

    int g = tid >> 6;
    int d = tid & 63;
    float acc = 0.0f;
    for (int t = g; t < n; t += 2) {
        int j = (t < n0) ? t : (r1lo + (t - n0));
        acc += sc[t] * g_v[(size_t)j * DM + head * HDIM + d];
    }
    red[tid] = acc;
    __syncthreads();
    if (tid < 64)
        g_ctx[(size_t)i * DM + head * HDIM + tid] = (red[tid] + red[64 + tid]) / denom;
}

// ---------------------------------------------------------------------------
// Launch
// ---------------------------------------------------------------------------
extern "C" void kernel_launch(void* const* d_in, const int* in_sizes, int n_in,
                              void* d_out, int out_size) {
    const int* inputs = (const int*)d_in[0];
    const float* embed = (const float*)d_in[2];
    const float* wq = (const float*)d_in[3];
    const float* wk = (const float*)d_in[4];
    const float* wv = (const float*)d_in[5];
    const float* wo = (const float*)d_in[6];
    const float* ln1s = (const float*)d_in[7];
    const float* ln1b = (const float*)d_in[8];
    const float* ln2s = (const float*)d_in[9];
    const float* ln2b = (const float*)d_in[10];
    const float* w1 = (const float*)d_in[11];
    const float* b1 = (const float*)d_in[12];
    const float* w2 = (const float*)d_in[13];
    const float* b2 = (const float*)d_in[14];
    const float* lnfs = (const float*)d_in[15];
    const float* lnfb = (const float*)d_in[16];
    float* out = (float*)d_out;

    float *xp, *hp, *qp, *kp, *vp, *cp, *yp;
    float *wqT, *wkT, *wvT, *woT, *w1T, *w2T;
    cudaGetSymbolAddress((void**)&xp, g_x);
    cudaGetSymbolAddress((void**)&hp, g_h);
    cudaGetSymbolAddress((void**)&qp, g_q);
    cudaGetSymbolAddress((void**)&kp, g_k);
    cudaGetSymbolAddress((void**)&vp, g_v);
    cudaGetSymbolAddress((void**)&cp, g_ctx);
    cudaGetSymbolAddress((void**)&yp, g_y1);
    cudaGetSymbolAddress((void**)&wqT, g_wqT);
    cudaGetSymbolAddress((void**)&wkT, g_wkT);
    cudaGetSymbolAddress((void**)&wvT, g_wvT);
    cudaGetSymbolAddress((void**)&woT, g_woT);
    cudaGetSymbolAddress((void**)&w1T, g_w1T);
    cudaGetSymbolAddress((void**)&w2T, g_w2T);

    cudaFuncSetAttribute(mma_gemm<0, 0, 0>, cudaFuncAttributeMaxDynamicSharedMemorySize, DYNSM);
    cudaFuncSetAttribute(mma_gemm<0, 0, 1>, cudaFuncAttributeMaxDynamicSharedMemorySize, DYNSM);
    cudaFuncSetAttribute(mma_gemm<1, 1, 0>, cudaFuncAttributeMaxDynamicSharedMemorySize, DYNSM);
    cudaFuncSetAttribute(mma_gemm<1, 0, 1>, cudaFuncAttributeMaxDynamicSharedMemorySize, DYNSM);

    dim3 tb(32, 8);
    transpose_kernel<<<dim3(32, 32, NL), tb>>>(wq, wqT, DM, DM);
    transpose_kernel<<<dim3(32, 32, NL), tb>>>(wk, wkT, DM, DM);
    transpose_kernel<<<dim3(32, 32, NL), tb>>>(wv, wvT, DM, DM);
    transpose_kernel<<<dim3(32, 32, NL), tb>>>(wo, woT, DM, DM);
    transpose_kernel<<<dim3(MLPD / 32, DM / 32, NL), tb>>>(w1, w1T, DM, MLPD);
    transpose_kernel<<<dim3(DM / 32, MLPD / 32, NL), tb>>>(w2, w2T, MLPD, DM);

    embed_kernel<<<SQ * DM / 256, 256>>>(inputs, embed);

    const size_t W_ATT = (size_t)DM * DM;
    const size_t W_MLP = (size_t)DM * MLPD;
    dim3 g_1024(DM / 128, SQ / 128);
    dim3 g_4096(MLPD / 128, SQ / 128);

    for (int l = 0; l < NL; l++) {
        ln_kernel<<<SQ, 256>>>(xp, ln1s + l * DM, ln1b + l * DM, hp);

        mma_gemm<0, 0, 0><<<g_1024, 256, DYNSM>>>(hp, wqT + l * W_ATT, nullptr, nullptr,
                                                  qp, DM, DM, 0.125f);
        mma_gemm<0, 0, 0><<<g_1024, 256, DYNSM>>>(hp, wkT + l * W_ATT, nullptr, nullptr,
                                                  kp, DM, DM, 1.0f);
        mma_gemm<0, 0, 0><<<g_1024, 256, DYNSM>>>(hp, wvT + l * W_ATT, nullptr, nullptr,
                                                  vp, DM, DM, 1.0f);

        attn_kernel<<<dim3(SQ, NH), 128>>>();

        mma_gemm<0, 0, 1><<<g_1024, 256, DYNSM>>>(cp, woT + l * W_ATT, nullptr, xp,
                                                  xp, DM, DM, 1.0f);

        ln_kernel<<<SQ, 256>>>(xp, ln2s + l * DM, ln2b + l * DM, hp);

        mma_gemm<1, 1, 0><<<g_4096, 256, DYNSM>>>(hp, w1T + l * W_MLP, b1 + l * MLPD,
                                                  nullptr, yp, DM, MLPD, 1.0f);
        mma_gemm<1, 0, 1><<<g_1024, 256, DYNSM>>>(yp, w2T + l * W_MLP, b2 + l * DM, xp,
                                                  xp, MLPD, DM, 1.0f);
    }

    ln_kernel<<<SQ, 256>>>(xp, lnfs, lnfb, out);
}

// round 8
// speedup vs baseline: 1.5409x; 1.5409x over previous
#include <cuda_runtime.h>
#include <cuda_bf16.h>
#include <math.h>
#include <stdint.h>

#define SQ   2048
#define DM   1024
#define NH   16
#define HDIM 64
#define MLPD 4096
#define NL   4
#define HALFW 256
#define NG   64

// ---------------- scratch (device globals; no allocation allowed) ----------
__device__ float g_x[SQ * DM];            // residual stream (fp32)
__device__ float g_qkv[SQ * 3 * DM];      // fused qkv output (fp32)
__device__ __nv_bfloat16 g_hh[SQ * DM];   // LN out hi
__device__ __nv_bfloat16 g_hl[SQ * DM];   // LN out lo
__device__ __nv_bfloat16 g_ch[SQ * DM];   // ctx hi
__device__ __nv_bfloat16 g_cl[SQ * DM];   // ctx lo
__device__ __nv_bfloat16 g_y1h[SQ * MLPD];
__device__ __nv_bfloat16 g_y1l[SQ * MLPD];
__device__ __nv_bfloat16 g_wqkvh[NL * 3 * DM * DM];
__device__ __nv_bfloat16 g_wqkvl[NL * 3 * DM * DM];
__device__ __nv_bfloat16 g_woh[NL * DM * DM];
__device__ __nv_bfloat16 g_wol[NL * DM * DM];
__device__ __nv_bfloat16 g_w1h[NL * DM * MLPD];
__device__ __nv_bfloat16 g_w1l[NL * DM * MLPD];
__device__ __nv_bfloat16 g_w2h[NL * MLPD * DM];
__device__ __nv_bfloat16 g_w2l[NL * MLPD * DM];

// ---------------- helpers ---------------------------------------------------
__device__ __forceinline__ uint32_t smem_u32(const void* p) {
    uint32_t a;
    asm("{ .reg .u64 t; cvta.to.shared.u64 t, %1; cvt.u32.u64 %0, t; }"
        : "=r"(a) : "l"(p));
    return a;
}

__device__ __forceinline__ void ldsm4(uint32_t* r, uint32_t addr) {
    asm volatile("ldmatrix.sync.aligned.m8n8.x4.shared.b16 {%0,%1,%2,%3}, [%4];"
                 : "=r"(r[0]), "=r"(r[1]), "=r"(r[2]), "=r"(r[3]) : "r"(addr));
}

__device__ __forceinline__ void mma_bf16(float* c, const uint32_t* a,
                                         const uint32_t* b) {
    asm volatile(
        "mma.sync.aligned.m16n8k16.row.col.f32.bf16.bf16.f32 "
        "{%0,%1,%2,%3}, {%4,%5,%6,%7}, {%8,%9}, {%0,%1,%2,%3};"
        : "+f"(c[0]), "+f"(c[1]), "+f"(c[2]), "+f"(c[3])
        : "r"(a[0]), "r"(a[1]), "r"(a[2]), "r"(a[3]), "r"(b[0]), "r"(b[1]));
}

#define CP16(dst, src) \
    asm volatile("cp.async.ca.shared.global [%0], [%1], 16;" ::"r"(dst), "l"(src) : "memory")
#define CPCOMMIT() asm volatile("cp.async.commit_group;" ::: "memory")

__device__ __forceinline__ void split_bf16(float v, __nv_bfloat16& h, __nv_bfloat16& l) {
    h = __float2bfloat16_rn(v);
    l = __float2bfloat16_rn(v - __bfloat162float(h));
}

// smem geometry (bytes)
#define ROWB  80            // 32 bf16 = 64B + 16B pad
#define PART  (128 * ROWB)  // 10240 B
#define BUFB  (4 * PART)    // Ah, Al, Bh, Bl
#define DYNSM (2 * BUFB)    // 81920 B

// ---------------------------------------------------------------------------
// bf16-split GEMM with pre-split operands.
// A_hi/A_lo [M,K] bf16, B_hi/B_lo [N,K] bf16. C = epi(A@B^T) (3-term split).
// 128x128x32 tile, 256 thr, cp.async double-buffered.
// ---------------------------------------------------------------------------
template <int BIAS, int RELU, int RESID, int OSPLIT>
__global__ __launch_bounds__(256) void mma_gemm(
    const __nv_bfloat16* __restrict__ Ah, const __nv_bfloat16* __restrict__ Al,
    const __nv_bfloat16* __restrict__ Bh, const __nv_bfloat16* __restrict__ Bl,
    const float* __restrict__ bias, const float* __restrict__ resid,
    float* __restrict__ Cf, __nv_bfloat16* __restrict__ Coh,
    __nv_bfloat16* __restrict__ Col, int K, int N) {
    extern __shared__ __align__(16) char dsm[];
    const uint32_t sbase = smem_u32(dsm);

    const int tid = threadIdx.x;
    const int wid = tid >> 5, lane = tid & 31;
    const int srow = tid >> 1, sseg = tid & 1;

    const __nv_bfloat16* pAh = Ah + ((size_t)blockIdx.y * 128 + srow) * (size_t)K;
    const __nv_bfloat16* pAl = Al + ((size_t)blockIdx.y * 128 + srow) * (size_t)K;
    const __nv_bfloat16* pBh = Bh + ((size_t)blockIdx.x * 128 + srow) * (size_t)K;
    const __nv_bfloat16* pBl = Bl + ((size_t)blockIdx.x * 128 + srow) * (size_t)K;

    float acc[4][4][4];
#pragma unroll
    for (int i = 0; i < 4; i++)
#pragma unroll
        for (int j = 0; j < 4; j++)
#pragma unroll
            for (int f = 0; f < 4; f++) acc[i][j][f] = 0.0f;

    const uint32_t dstoff = (uint32_t)(srow * ROWB + sseg * 32);
    const int CH = K >> 5;

#define ISSUE(c)                                                       \
    {                                                                  \
        uint32_t b = sbase + (uint32_t)((c) & 1) * BUFB + dstoff;      \
        size_t off = (size_t)(c) * 32 + sseg * 16;                     \
        CP16(b, pAh + off);                                            \
        CP16(b + 16, pAh + off + 8);                                   \
        CP16(b + PART, pAl + off);                                     \
        CP16(b + PART + 16, pAl + off + 8);                            \
        CP16(b + 2 * PART, pBh + off);                                 \
        CP16(b + 2 * PART + 16, pBh + off + 8);                        \
        CP16(b + 3 * PART, pBl + off);                                 \
        CP16(b + 3 * PART + 16, pBl + off + 8);                        \
        CPCOMMIT();                                                    \
    }

    ISSUE(0);

    const int m_base = (wid & 1) * 64;
    const int n_base = (wid >> 1) * 32;
    const int lgrp = lane >> 3, lr = lane & 7;

    for (int c = 0; c < CH; c++) {
        if (c + 1 < CH) {
            ISSUE(c + 1);
            asm volatile("cp.async.wait_group 1;" ::: "memory");
        } else {
            asm volatile("cp.async.wait_group 0;" ::: "memory");
        }
        __syncthreads();

        const uint32_t sb0 = sbase + (uint32_t)(c & 1) * BUFB;
#pragma unroll
        for (int ks = 0; ks < 2; ks++) {
            uint32_t bh[4][2], bl[4][2];
#pragma unroll
            for (int p = 0; p < 2; p++) {
                uint32_t row = (uint32_t)(n_base + p * 16 + (lgrp >> 1) * 8 + lr);
                uint32_t ad = sb0 + 2 * PART + row * ROWB + ks * 32 + (lgrp & 1) * 16;
                uint32_t t[4];
                ldsm4(t, ad);
                bh[2 * p][0] = t[0]; bh[2 * p][1] = t[1];
                bh[2 * p + 1][0] = t[2]; bh[2 * p + 1][1] = t[3];
                ldsm4(t, ad + PART);
                bl[2 * p][0] = t[0]; bl[2 * p][1] = t[1];
                bl[2 * p + 1][0] = t[2]; bl[2 * p + 1][1] = t[3];
            }
#pragma unroll
            for (int mt = 0; mt < 4; mt++) {
                uint32_t row = (uint32_t)(m_base + mt * 16 + (lgrp & 1) * 8 + lr);
                uint32_t ad = sb0 + row * ROWB + ks * 32 + (lgrp >> 1) * 16;
                uint32_t ah[4], al[4];
                ldsm4(ah, ad);
                ldsm4(al, ad + PART);
#pragma unroll
                for (int nt = 0; nt < 4; nt++) {
                    mma_bf16(acc[mt][nt], ah, bh[nt]);
                    mma_bf16(acc[mt][nt], ah, bl[nt]);
                    mma_bf16(acc[mt][nt], al, bh[nt]);
                }
            }
        }
        __syncthreads();
    }

    // epilogue
    const int m0 = blockIdx.y * 128 + m_base;
    const int n0 = blockIdx.x * 128 + n_base;
    const int mr = lane >> 2, nc = (lane & 3) * 2;
#pragma unroll
    for (int mt = 0; mt < 4; mt++) {
#pragma unroll
        for (int half = 0; half < 2; half++) {
            const size_t m = (size_t)(m0 + mt * 16 + mr + half * 8);
#pragma unroll
            for (int nt = 0; nt < 4; nt++) {
                const int n = n0 + nt * 8 + nc;
                float v0 = acc[mt][nt][2 * half];
                float v1 = acc[mt][nt][2 * half + 1];
                if (BIAS) { v0 += bias[n]; v1 += bias[n + 1]; }
                if (RELU) { v0 = fmaxf(v0, 0.0f); v1 = fmaxf(v1, 0.0f); }
                if (RESID) {
                    float2 r2 = *(const float2*)(resid + m * N + n);
                    v0 += r2.x; v1 += r2.y;
                }
                if (OSPLIT) {
                    __nv_bfloat16 h0, l0, h1, l1;
                    split_bf16(v0, h0, l0);
                    split_bf16(v1, h1, l1);
                    __nv_bfloat162 hp; hp.x = h0; hp.y = h1;
                    __nv_bfloat162 lp; lp.x = l0; lp.y = l1;
                    *(__nv_bfloat162*)(Coh + m * N + n) = hp;
                    *(__nv_bfloat162*)(Col + m * N + n) = lp;
                } else {
                    float2 o; o.x = v0; o.y = v1;
                    *(float2*)(Cf + m * N + n) = o;
                }
            }
        }
    }
}

// ---------------------------------------------------------------------------
// Weight transpose + bf16 split: in fp32 [R,C] (xalpha) -> hi/lo bf16 [C,R]
// ---------------------------------------------------------------------------
__global__ void transpose_split(const float* __restrict__ in,
                                __nv_bfloat16* __restrict__ oh,
                                __nv_bfloat16* __restrict__ ol,
                                int R, int C, float alpha,
                                long in_ls, long out_ls) {
    __shared__ float t[32][33];
    const float* ip = in + (size_t)blockIdx.z * in_ls;
    __nv_bfloat16* ohp = oh + (size_t)blockIdx.z * out_ls;
    __nv_bfloat16* olp = ol + (size_t)blockIdx.z * out_ls;
    const int c0 = blockIdx.x * 32, r0 = blockIdx.y * 32;
    for (int k = threadIdx.y; k < 32; k += 8)
        t[k][threadIdx.x] = ip[(size_t)(r0 + k) * C + c0 + threadIdx.x] * alpha;
    __syncthreads();
    for (int k = threadIdx.y; k < 32; k += 8) {
        float v = t[threadIdx.x][k];
        __nv_bfloat16 hv, lv;
        split_bf16(v, hv, lv);
        size_t o = (size_t)(c0 + k) * R + r0 + threadIdx.x;
        ohp[o] = hv;
        olp[o] = lv;
    }
}

// ---------------------------------------------------------------------------
// Embedding + sinusoidal positional encoding
// ---------------------------------------------------------------------------
__global__ void embed_kernel(const int* __restrict__ inputs,
                             const float* __restrict__ emb) {
    int idx = blockIdx.x * blockDim.x + threadIdx.x;
    int s = idx >> 10;
    int d = idx & 1023;
    int tok = inputs[s];
    float val = emb[tok * DM + d];
    int k2 = d >> 1;
    float div = expf((float)(2 * k2) * (-9.210340371976184f / 1024.0f));
    float ang = (float)s * div;
    val += (d & 1) ? cosf(ang) : sinf(ang);
    g_x[idx] = val;
}

// ---------------------------------------------------------------------------
// LayerNorm (SPLIT=1: write bf16 hi/lo; SPLIT=0: write fp32)
// ---------------------------------------------------------------------------
__device__ __forceinline__ float block_reduce_sum(float v) {
    __shared__ float sm[8];
    int lane = threadIdx.x & 31;
    int warp = threadIdx.x >> 5;
#pragma unroll
    for (int o = 16; o; o >>= 1) v += __shfl_xor_sync(0xffffffffu, v, o);
    if (lane == 0) sm[warp] = v;
    __syncthreads();
    if (warp == 0) {
        v = (lane < 8) ? sm[lane] : 0.0f;
#pragma unroll
        for (int o = 4; o; o >>= 1) v += __shfl_xor_sync(0xffffffffu, v, o);
        if (lane == 0) sm[0] = v;
    }
    __syncthreads();
    float r = sm[0];
    __syncthreads();
    return r;
}

template <int SPLIT>
__global__ void ln_kernel(const float* __restrict__ in,
                          const float* __restrict__ scale,
                          const float* __restrict__ bias,
                          float* __restrict__ outf,
                          __nv_bfloat16* __restrict__ oh,
                          __nv_bfloat16* __restrict__ ol) {
    int row = blockIdx.x;
    float4 v = ((const float4*)(in + row * DM))[threadIdx.x];
    float mu = block_reduce_sum(v.x + v.y + v.z + v.w) * (1.0f / DM);
    float dx = v.x - mu, dy = v.y - mu, dz = v.z - mu, dw = v.w - mu;
    float var = block_reduce_sum(dx * dx + dy * dy + dz * dz + dw * dw) * (1.0f / DM);
    float rs = rsqrtf(var + 1e-6f);
    float4 s4 = ((const float4*)scale)[threadIdx.x];
    float4 b4 = ((const float4*)bias)[threadIdx.x];
    float4 o;
    o.x = dx * rs * s4.x + b4.x;
    o.y = dy * rs * s4.y + b4.y;
    o.z = dz * rs * s4.z + b4.z;
    o.w = dw * rs * s4.w + b4.w;
    if (SPLIT) {
        __nv_bfloat16 h0, l0, h1, l1, h2, l2, h3, l3;
        split_bf16(o.x, h0, l0); split_bf16(o.y, h1, l1);
        split_bf16(o.z, h2, l2); split_bf16(o.w, h3, l3);
        size_t base = (size_t)row * DM + threadIdx.x * 4;
        __nv_bfloat162 p0, p1;
        p0.x = h0; p0.y = h1; p1.x = h2; p1.y = h3;
        *(__nv_bfloat162*)(oh + base) = p0;
        *(__nv_bfloat162*)(oh + base + 2) = p1;
        p0.x = l0; p0.y = l1; p1.x = l2; p1.y = l3;
        *(__nv_bfloat162*)(ol + base) = p0;
        *(__nv_bfloat162*)(ol + base + 2) = p1;
    } else {
        ((float4*)(outf + row * DM))[threadIdx.x] = o;
    }
}

// ---------------------------------------------------------------------------
// Sparse attention: 16 queries x 1 head per block, online softmax.
// Keys: all j (global tile i0<NG) or [0,NG) U [jlo,jhi) with per-(i,j) mask.
// Reads fused qkv (fp32), writes ctx as split bf16.
// ---------------------------------------------------------------------------
#define QT 16
#define KC 64
__global__ __launch_bounds__(256) void attn_kernel(
    const float* __restrict__ qkv,
    __nv_bfloat16* __restrict__ ch, __nv_bfloat16* __restrict__ cl) {
    __shared__ float qs[QT * 68];
    __shared__ float kv[KC * 68];
    __shared__ float sb[QT * 65];
    __shared__ float st_m[QT], st_l[QT], st_r[QT];

    const int i0 = blockIdx.x * QT;
    const int h = blockIdx.y;
    const int tid = threadIdx.x;
    const bool gq = (i0 < NG);

    // load Q tile
    {
        int r = tid >> 4, d = (tid & 15) * 4;
        float4 qv = *(const float4*)(qkv + (size_t)(i0 + r) * (3 * DM) + h * HDIM + d);
        *(float4*)&qs[r * 68 + d] = qv;
    }
    if (tid < QT) { st_m[tid] = -1e30f; st_l[tid] = 0.0f; }

    const int jlo = max(NG, i0 - HALFW);
    const int jhi = min(SQ, i0 + QT - 1 + HALFW + 1);
    const int n = gq ? SQ : (NG + jhi - jlo);

    // PV accumulators: thread (q, d4)
    const int pq = tid >> 4;
    const int pd = (tid & 15) * 4;
    float4 acc = make_float4(0.f, 0.f, 0.f, 0.f);

    const int qb = tid & 7;
    const int kb = (tid >> 3) * 2;
    const int w = tid >> 5, lane = tid & 31;
    __syncthreads();

    for (int t0 = 0; t0 < n; t0 += KC) {
        const int cnt = min(KC, n - t0);
        // stage K chunk
        {
            int r = tid >> 2, doff = (tid & 3) * 16;
            if (r < cnt) {
                int t = t0 + r;
                int j = (gq || t < NG) ? t : (jlo + (t - NG));
                const float* kr = qkv + (size_t)j * (3 * DM) + DM + h * HDIM + doff;
                float* dst = &kv[r * 68 + doff];
                *(float4*)(dst + 0) = *(const float4*)(kr + 0);
                *(float4*)(dst + 4) = *(const float4*)(kr + 4);
                *(float4*)(dst + 8) = *(const float4*)(kr + 8);
                *(float4*)(dst + 12) = *(const float4*)(kr + 12);
            }
        }
        __syncthreads();
        // scores: thread = (2q, 2k)
        if (kb < cnt) {
            float a00 = 0, a01 = 0, a10 = 0, a11 = 0;
#pragma unroll
            for (int d = 0; d < 64; d += 4) {
                float4 q0 = *(float4*)&qs[qb * 68 + d];
                float4 q1 = *(float4*)&qs[(qb + 8) * 68 + d];
                float4 k0 = *(float4*)&kv[kb * 68 + d];
                float4 k1 = *(float4*)&kv[(kb + 1) * 68 + d];
                a00 += q0.x * k0.x + q0.y * k0.y + q0.z * k0.z + q0.w * k0.w;
                a01 += q0.x * k1.x + q0.y * k1.y + q0.z * k1.z + q0.w * k1.w;
                a10 += q1.x * k0.x + q1.y * k0.y + q1.z * k0.z + q1.w * k0.w;
                a11 += q1.x * k1.x + q1.y * k1.y + q1.z * k1.z + q1.w * k1.w;
            }
            if (gq) {
                sb[qb * 65 + kb] = a00;
                sb[(qb + 8) * 65 + kb] = a10;
                if (kb + 1 < cnt) {
                    sb[qb * 65 + kb + 1] = a01;
                    sb[(qb + 8) * 65 + kb + 1] = a11;
                }
            } else {
                int t = t0 + kb, t1 = t + 1;
                int j0 = (t < NG) ? t : (jlo + (t - NG));
                int j1 = (t1 < NG) ? t1 : (jlo + (t1 - NG));
                int iA = i0 + qb, iB = i0 + qb + 8;
                bool m00 = (j0 < NG) || (abs(iA - j0) <= HALFW);
                bool m10 = (j0 < NG) || (abs(iB - j0) <= HALFW);
                sb[qb * 65 + kb] = m00 ? a00 : -1e9f;
                sb[(qb + 8) * 65 + kb] = m10 ? a10 : -1e9f;
                if (kb + 1 < cnt) {
                    bool m01 = (j1 < NG) || (abs(iA - j1) <= HALFW);
                    bool m11 = (j1 < NG) || (abs(iB - j1) <= HALFW);
                    sb[qb * 65 + kb + 1] = m01 ? a01 : -1e9f;
                    sb[(qb + 8) * 65 + kb + 1] = m11 ? a11 : -1e9f;
                }
            }
        }
        __syncthreads();
        // online softmax update: warp w handles rows w, w+8
        if (w < 8) {
#pragma unroll
            for (int rr = 0; rr < 2; rr++) {
                int r = w + rr * 8;
                float cm = -1e30f;
                for (int t = lane; t < cnt; t += 32) cm = fmaxf(cm, sb[r * 65 + t]);
#pragma unroll
                for (int o = 16; o; o >>= 1)
                    cm = fmaxf(cm, __shfl_xor_sync(0xffffffffu, cm, o));
                float m_old = st_m[r];
                float m_new = fmaxf(m_old, cm);
                float sum = 0.0f;
                for (int t = lane; t < cnt; t += 32) {
                    float e = expf(sb[r * 65 + t] - m_new);
                    sb[r * 65 + t] = e;
                    sum += e;
                }
#pragma unroll
                for (int o = 16; o; o >>= 1) sum += __shfl_xor_sync(0xffffffffu, sum, o);
                if (lane == 0) {
                    float rsc = expf(m_old - m_new);
                    st_r[r] = rsc;
                    st_l[r] = st_l[r] * rsc + sum;
                    st_m[r] = m_new;
                }
            }
        }
        __syncthreads();
        // stage V chunk (reuse kv buffer)
        {
            int r = tid >> 2, doff = (tid & 3) * 16;
            if (r < cnt) {
                int t = t0 + r;
                int j = (gq || t < NG) ? t : (jlo + (t - NG));
                const float* vr = qkv + (size_t)j * (3 * DM) + 2 * DM + h * HDIM + doff;
                float* dst = &kv[r * 68 + doff];
                *(float4*)(dst + 0) = *(const float4*)(vr + 0);
                *(float4*)(dst + 4) = *(const float4*)(vr + 4);
                *(float4*)(dst + 8) = *(const float4*)(vr + 8);
                *(float4*)(dst + 12) = *(const float4*)(vr + 12);
            }
        }
        __syncthreads();
        // PV update
        {
            float rsc = st_r[pq];
            acc.x *= rsc; acc.y *= rsc; acc.z *= rsc; acc.w *= rsc;
            for (int kk = 0; kk < cnt; kk++) {
                float p = sb[pq * 65 + kk];
                float4 vv = *(float4*)&kv[kk * 68 + pd];
                acc.x += p * vv.x; acc.y += p * vv.y;
                acc.z += p * vv.z; acc.w += p * vv.w;
            }
        }
        __syncthreads();
    }

    // write ctx (split bf16)
    {
        float inv = 1.0f / st_l[pq];
        float o0 = acc.x * inv, o1 = acc.y * inv, o2 = acc.z * inv, o3 = acc.w * inv;
        __nv_bfloat16 h0, l0, h1, l1, h2, l2, h3, l3;
        split_bf16(o0, h0, l0); split_bf16(o1, h1, l1);
        split_bf16(o2, h2, l2); split_bf16(o3, h3, l3);
        size_t base = (size_t)(i0 + pq) * DM + h * HDIM + pd;
        __nv_bfloat162 p0, p1;
        p0.x = h0; p0.y = h1; p1.x = h2; p1.y = h3;
        *(__nv_bfloat162*)(ch + base) = p0;
        *(__nv_bfloat162*)(ch + base + 2) = p1;
        p0.x = l0; p0.y = l1; p1.x = l2; p1.y = l3;
        *(__nv_bfloat162*)(cl + base) = p0;
        *(__nv_bfloat162*)(cl + base + 2) = p1;
    }
}

// ---------------------------------------------------------------------------
// Launch
// ---------------------------------------------------------------------------
extern "C" void kernel_launch(void* const* d_in, const int* in_sizes, int n_in,
                              void* d_out, int out_size) {
    const int* inputs = (const int*)d_in[0];
    const float* embed = (const float*)d_in[2];
    const float* wq = (const float*)d_in[3];
    const float* wk = (const float*)d_in[4];
    const float* wv = (const float*)d_in[5];
    const float* wo = (const float*)d_in[6];
    const float* ln1s = (const float*)d_in[7];
    const float* ln1b = (const float*)d_in[8];
    const float* ln2s = (const float*)d_in[9];
    const float* ln2b = (const float*)d_in[10];
    const float* w1 = (const float*)d_in[11];
    const float* b1 = (const float*)d_in[12];
    const float* w2 = (const float*)d_in[13];
    const float* b2 = (const float*)d_in[14];
    const float* lnfs = (const float*)d_in[15];
    const float* lnfb = (const float*)d_in[16];
    float* out = (float*)d_out;

    float *xp, *qkvp;
    __nv_bfloat16 *hh, *hl, *chp, *clp, *y1h, *y1l;
    __nv_bfloat16 *wqkvh, *wqkvl, *woh, *wol, *w1h, *w1l, *w2h, *w2l;
    cudaGetSymbolAddress((void**)&xp, g_x);
    cudaGetSymbolAddress((void**)&qkvp, g_qkv);
    cudaGetSymbolAddress((void**)&hh, g_hh);
    cudaGetSymbolAddress((void**)&hl, g_hl);
    cudaGetSymbolAddress((void**)&chp, g_ch);
    cudaGetSymbolAddress((void**)&clp, g_cl);
    cudaGetSymbolAddress((void**)&y1h, g_y1h);
    cudaGetSymbolAddress((void**)&y1l, g_y1l);
    cudaGetSymbolAddress((void**)&wqkvh, g_wqkvh);
    cudaGetSymbolAddress((void**)&wqkvl, g_wqkvl);
    cudaGetSymbolAddress((void**)&woh, g_woh);
    cudaGetSymbolAddress((void**)&wol, g_wol);
    cudaGetSymbolAddress((void**)&w1h, g_w1h);
    cudaGetSymbolAddress((void**)&w1l, g_w1l);
    cudaGetSymbolAddress((void**)&w2h, g_w2h);
    cudaGetSymbolAddress((void**)&w2l, g_w2l);

    cudaFuncSetAttribute(mma_gemm<0, 0, 0, 0>, cudaFuncAttributeMaxDynamicSharedMemorySize, DYNSM);
    cudaFuncSetAttribute(mma_gemm<0, 0, 1, 0>, cudaFuncAttributeMaxDynamicSharedMemorySize, DYNSM);
    cudaFuncSetAttribute(mma_gemm<1, 1, 0, 1>, cudaFuncAttributeMaxDynamicSharedMemorySize, DYNSM);
    cudaFuncSetAttribute(mma_gemm<1, 0, 1, 0>, cudaFuncAttributeMaxDynamicSharedMemorySize, DYNSM);

    const long WA = (long)DM * DM;
    const long WM = (long)DM * MLPD;
    dim3 tb(32, 8);
    // fused qkv weights: rows 0..1023 = q (x0.125), 1024.. = k, 2048.. = v
    transpose_split<<<dim3(32, 32, NL), tb>>>(wq, wqkvh, wqkvl, DM, DM, 0.125f, WA, 3 * WA);
    transpose_split<<<dim3(32, 32, NL), tb>>>(wk, wqkvh + WA, wqkvl + WA, DM, DM, 1.0f, WA, 3 * WA);
    transpose_split<<<dim3(32, 32, NL), tb>>>(wv, wqkvh + 2 * WA, wqkvl + 2 * WA, DM, DM, 1.0f, WA, 3 * WA);
    transpose_split<<<dim3(32, 32, NL), tb>>>(wo, woh, wol, DM, DM, 1.0f, WA, WA);
    transpose_split<<<dim3(MLPD / 32, DM / 32, NL), tb>>>(w1, w1h, w1l, DM, MLPD, 1.0f, WM, WM);
    transpose_split<<<dim3(DM / 32, MLPD / 32, NL), tb>>>(w2, w2h, w2l, MLPD, DM, 1.0f, WM, WM);

    embed_kernel<<<SQ * DM / 256, 256>>>(inputs, embed);

    dim3 g_qkvg(3 * DM / 128, SQ / 128);   // (24,16)
    dim3 g_1024(DM / 128, SQ / 128);       // (8,16)
    dim3 g_4096(MLPD / 128, SQ / 128);     // (32,16)

    for (int l = 0; l < NL; l++) {
        ln_kernel<1><<<SQ, 256>>>(xp, ln1s + l * DM, ln1b + l * DM, nullptr, hh, hl);

        mma_gemm<0, 0, 0, 0><<<g_qkvg, 256, DYNSM>>>(
            hh, hl, wqkvh + (size_t)l * 3 * WA, wqkvl + (size_t)l * 3 * WA,
            nullptr, nullptr, qkvp, nullptr, nullptr, DM, 3 * DM);

        attn_kernel<<<dim3(SQ / QT, NH), 256>>>(qkvp, chp, clp);

        mma_gemm<0, 0, 1, 0><<<g_1024, 256, DYNSM>>>(
            chp, clp, woh + (size_t)l * WA, wol + (size_t)l * WA,
            nullptr, xp, xp, nullptr, nullptr, DM, DM);

        ln_kernel<1><<<SQ, 256>>>(xp, ln2s + l * DM, ln2b + l * DM, nullptr, hh, hl);

        mma_gemm<1, 1, 0, 1><<<g_4096, 256, DYNSM>>>(
            hh, hl, w1h + (size_t)l * WM, w1l + (size_t)l * WM,
            b1 + l * MLPD, nullptr, nullptr, y1h, y1l, DM, MLPD);

        mma_gemm<1, 0, 1, 0><<<g_1024, 256, DYNSM>>>(
            y1h, y1l, w2h + (size_t)l * WM, w2l + (size_t)l * WM,
            b2 + l * DM, xp, xp, nullptr, nullptr, MLPD, DM);
    }

    ln_kernel<0><<<SQ, 256>>>(xp, lnfs, lnfb, out, nullptr, nullptr);
}

// round 9
// speedup vs baseline: 1.6012x; 1.0391x over previous
#include <cuda_runtime.h>
#include <cuda_bf16.h>
#include <math.h>
#include <stdint.h>

#define SQ   2048
#define DM   1024
#define NH   16
#define HDIM 64
#define MLPD 4096
#define NL   4
#define HALFW 256
#define NG   64

// ---------------- scratch (device globals; no allocation allowed) ----------
__device__ float g_x[SQ * DM];            // residual stream (fp32)
__device__ float g_qkv[SQ * 3 * DM];      // fused qkv output (fp32)
__device__ __nv_bfloat16 g_hh[SQ * DM];   // LN out hi
__device__ __nv_bfloat16 g_hl[SQ * DM];   // LN out lo
__device__ __nv_bfloat16 g_ch[SQ * DM];   // ctx hi
__device__ __nv_bfloat16 g_cl[SQ * DM];   // ctx lo
__device__ __nv_bfloat16 g_y1h[SQ * MLPD];
__device__ __nv_bfloat16 g_y1l[SQ * MLPD];
__device__ __nv_bfloat16 g_wqkvh[NL * 3 * DM * DM];
__device__ __nv_bfloat16 g_wqkvl[NL * 3 * DM * DM];
__device__ __nv_bfloat16 g_woh[NL * DM * DM];
__device__ __nv_bfloat16 g_wol[NL * DM * DM];
__device__ __nv_bfloat16 g_w1h[NL * DM * MLPD];
__device__ __nv_bfloat16 g_w1l[NL * DM * MLPD];
__device__ __nv_bfloat16 g_w2h[NL * MLPD * DM];
__device__ __nv_bfloat16 g_w2l[NL * MLPD * DM];

// ---------------- helpers ---------------------------------------------------
__device__ __forceinline__ uint32_t smem_u32(const void* p) {
    uint32_t a;
    asm("{ .reg .u64 t; cvta.to.shared.u64 t, %1; cvt.u32.u64 %0, t; }"
        : "=r"(a) : "l"(p));
    return a;
}

__device__ __forceinline__ void ldsm4(uint32_t* r, uint32_t addr) {
    asm volatile("ldmatrix.sync.aligned.m8n8.x4.shared.b16 {%0,%1,%2,%3}, [%4];"
                 : "=r"(r[0]), "=r"(r[1]), "=r"(r[2]), "=r"(r[3]) : "r"(addr));
}

__device__ __forceinline__ void mma_bf16(float* c, const uint32_t* a,
                                         const uint32_t* b) {
    asm volatile(
        "mma.sync.aligned.m16n8k16.row.col.f32.bf16.bf16.f32 "
        "{%0,%1,%2,%3}, {%4,%5,%6,%7}, {%8,%9}, {%0,%1,%2,%3};"
        : "+f"(c[0]), "+f"(c[1]), "+f"(c[2]), "+f"(c[3])
        : "r"(a[0]), "r"(a[1]), "r"(a[2]), "r"(a[3]), "r"(b[0]), "r"(b[1]));
}

#define CP16(dst, src) \
    asm volatile("cp.async.ca.shared.global [%0], [%1], 16;" ::"r"(dst), "l"(src) : "memory")
#define CPCOMMIT() asm volatile("cp.async.commit_group;" ::: "memory")

__device__ __forceinline__ void split_bf16(float v, __nv_bfloat16& h, __nv_bfloat16& l) {
    h = __float2bfloat16_rn(v);
    l = __float2bfloat16_rn(v - __bfloat162float(h));
}

// smem geometry (bytes): swizzled, no padding.
// Row = 32 bf16 = 64B = 4 x 16B groups; phys group = logical ^ ((row>>1)&3).
#define ROWB  64
#define PART  (128 * ROWB)   // 8192 B
#define BUFB  (4 * PART)     // 32768 B: Ah, Al, Bh, Bl
#define DYNSM (2 * BUFB + 128)

__device__ __forceinline__ uint32_t swz(uint32_t row, uint32_t g16) {
    return row * ROWB + ((g16 ^ ((row >> 1) & 3u)) << 4);
}

// ---------------------------------------------------------------------------
// bf16-split GEMM with pre-split operands.
// A_hi/A_lo [M,K] bf16, B_hi/B_lo [N,K] bf16. C = epi(A@B^T) (3-term split).
// 128x128x32 tile, 256 thr, 2 CTAs/SM, cp.async 2 chunks deep.
// ---------------------------------------------------------------------------
template <int BIAS, int RELU, int RESID, int OSPLIT>
__global__ __launch_bounds__(256, 2) void mma_gemm(
    const __nv_bfloat16* __restrict__ Ah, const __nv_bfloat16* __restrict__ Al,
    const __nv_bfloat16* __restrict__ Bh, const __nv_bfloat16* __restrict__ Bl,
    const float* __restrict__ bias, const float* __restrict__ resid,
    float* __restrict__ Cf, __nv_bfloat16* __restrict__ Coh,
    __nv_bfloat16* __restrict__ Col, int K, int N) {
    extern __shared__ __align__(16) char dsm[];
    const uint32_t sbase = (smem_u32(dsm) + 127u) & ~127u;

    const int tid = threadIdx.x;
    const int wid = tid >> 5, lane = tid & 31;
    const int srow = tid >> 1, sseg = tid & 1;

    const __nv_bfloat16* pAh = Ah + ((size_t)blockIdx.y * 128 + srow) * (size_t)K;
    const __nv_bfloat16* pAl = Al + ((size_t)blockIdx.y * 128 + srow) * (size_t)K;
    const __nv_bfloat16* pBh = Bh + ((size_t)blockIdx.x * 128 + srow) * (size_t)K;
    const __nv_bfloat16* pBl = Bl + ((size_t)blockIdx.x * 128 + srow) * (size_t)K;

    float acc[4][4][4];
#pragma unroll
    for (int i = 0; i < 4; i++)
#pragma unroll
        for (int j = 0; j < 4; j++)
#pragma unroll
            for (int f = 0; f < 4; f++) acc[i][j][f] = 0.0f;

    // cp.async destinations for this thread (two 16B groups per row-half)
    const uint32_t dA = swz((uint32_t)srow, (uint32_t)(2 * sseg));
    const uint32_t dB = swz((uint32_t)srow, (uint32_t)(2 * sseg + 1));
    const int CH = K >> 5;

#define ISSUE(c)                                                        \
    {                                                                   \
        uint32_t b = sbase + (uint32_t)((c) & 1) * BUFB;                \
        size_t off = (size_t)(c) * 32 + sseg * 16;                      \
        CP16(b + dA, pAh + off);                                        \
        CP16(b + dB, pAh + off + 8);                                    \
        CP16(b + PART + dA, pAl + off);                                 \
        CP16(b + PART + dB, pAl + off + 8);                             \
        CP16(b + 2 * PART + dA, pBh + off);                             \
        CP16(b + 2 * PART + dB, pBh + off + 8);                         \
        CP16(b + 3 * PART + dA, pBl + off);                             \
        CP16(b + 3 * PART + dB, pBl + off + 8);                         \
        CPCOMMIT();                                                     \
    }

    ISSUE(0);
    ISSUE(1);

    const int m_base = (wid & 1) * 64;
    const int n_base = (wid >> 1) * 32;
    const int lgrp = lane >> 3, lr = lane & 7;

    for (int c = 0; c < CH; c++) {
        if (c + 1 < CH) {
            asm volatile("cp.async.wait_group 1;" ::: "memory");
        } else {
            asm volatile("cp.async.wait_group 0;" ::: "memory");
        }
        __syncthreads();

        const uint32_t sb0 = sbase + (uint32_t)(c & 1) * BUFB;
#pragma unroll
        for (int ks = 0; ks < 2; ks++) {
            uint32_t bh[4][2], bl[4][2];
#pragma unroll
            for (int p = 0; p < 2; p++) {
                uint32_t row = (uint32_t)(n_base + p * 16 + (lgrp >> 1) * 8 + lr);
                uint32_t ad = sb0 + 2 * PART + swz(row, (uint32_t)(ks * 2 + (lgrp & 1)));
                uint32_t t[4];
                ldsm4(t, ad);
                bh[2 * p][0] = t[0]; bh[2 * p][1] = t[1];
                bh[2 * p + 1][0] = t[2]; bh[2 * p + 1][1] = t[3];
                ldsm4(t, ad + PART);
                bl[2 * p][0] = t[0]; bl[2 * p][1] = t[1];
                bl[2 * p + 1][0] = t[2]; bl[2 * p + 1][1] = t[3];
            }
#pragma unroll
            for (int mt = 0; mt < 4; mt++) {
                uint32_t row = (uint32_t)(m_base + mt * 16 + (lgrp & 1) * 8 + lr);
                uint32_t ad = sb0 + swz(row, (uint32_t)(ks * 2 + (lgrp >> 1)));
                uint32_t ah[4], al[4];
                ldsm4(ah, ad);
                ldsm4(al, ad + PART);
#pragma unroll
                for (int nt = 0; nt < 4; nt++) {
                    mma_bf16(acc[mt][nt], ah, bh[nt]);
                    mma_bf16(acc[mt][nt], ah, bl[nt]);
                    mma_bf16(acc[mt][nt], al, bh[nt]);
                }
            }
        }
        __syncthreads();
        if (c + 2 < CH) ISSUE(c + 2);
    }

    // epilogue
    const int m0 = blockIdx.y * 128 + m_base;
    const int n0 = blockIdx.x * 128 + n_base;
    const int mr = lane >> 2, nc = (lane & 3) * 2;
#pragma unroll
    for (int mt = 0; mt < 4; mt++) {
#pragma unroll
        for (int half = 0; half < 2; half++) {
            const size_t m = (size_t)(m0 + mt * 16 + mr + half * 8);
#pragma unroll
            for (int nt = 0; nt < 4; nt++) {
                const int n = n0 + nt * 8 + nc;
                float v0 = acc[mt][nt][2 * half];
                float v1 = acc[mt][nt][2 * half + 1];
                if (BIAS) { v0 += bias[n]; v1 += bias[n + 1]; }
                if (RELU) { v0 = fmaxf(v0, 0.0f); v1 = fmaxf(v1, 0.0f); }
                if (RESID) {
                    float2 r2 = *(const float2*)(resid + m * N + n);
                    v0 += r2.x; v1 += r2.y;
                }
                if (OSPLIT) {
                    __nv_bfloat16 h0, l0, h1, l1;
                    split_bf16(v0, h0, l0);
                    split_bf16(v1, h1, l1);
                    __nv_bfloat162 hp; hp.x = h0; hp.y = h1;
                    __nv_bfloat162 lp; lp.x = l0; lp.y = l1;
                    *(__nv_bfloat162*)(Coh + m * N + n) = hp;
                    *(__nv_bfloat162*)(Col + m * N + n) = lp;
                } else {
                    float2 o; o.x = v0; o.y = v1;
                    *(float2*)(Cf + m * N + n) = o;
                }
            }
        }
    }
}

// ---------------------------------------------------------------------------
// Weight transpose + bf16 split: in fp32 [R,C] (xalpha) -> hi/lo bf16 [C,R]
// ---------------------------------------------------------------------------
__global__ void transpose_split(const float* __restrict__ in,
                                __nv_bfloat16* __restrict__ oh,
                                __nv_bfloat16* __restrict__ ol,
                                int R, int C, float alpha,
                                long in_ls, long out_ls) {
    __shared__ float t[32][33];
    const float* ip = in + (size_t)blockIdx.z * in_ls;
    __nv_bfloat16* ohp = oh + (size_t)blockIdx.z * out_ls;
    __nv_bfloat16* olp = ol + (size_t)blockIdx.z * out_ls;
    const int c0 = blockIdx.x * 32, r0 = blockIdx.y * 32;
    for (int k = threadIdx.y; k < 32; k += 8)
        t[k][threadIdx.x] = ip[(size_t)(r0 + k) * C + c0 + threadIdx.x] * alpha;
    __syncthreads();
    for (int k = threadIdx.y; k < 32; k += 8) {
        float v = t[threadIdx.x][k];
        __nv_bfloat16 hv, lv;
        split_bf16(v, hv, lv);
        size_t o = (size_t)(c0 + k) * R + r0 + threadIdx.x;
        ohp[o] = hv;
        olp[o] = lv;
    }
}

// ---------------------------------------------------------------------------
// Embedding + sinusoidal positional encoding
// ---------------------------------------------------------------------------
__global__ void embed_kernel(const int* __restrict__ inputs,
                             const float* __restrict__ emb) {
    int idx = blockIdx.x * blockDim.x + threadIdx.x;
    int s = idx >> 10;
    int d = idx & 1023;
    int tok = inputs[s];
    float val = emb[tok * DM + d];
    int k2 = d >> 1;
    float div = expf((float)(2 * k2) * (-9.210340371976184f / 1024.0f));
    float ang = (float)s * div;
    val += (d & 1) ? cosf(ang) : sinf(ang);
    g_x[idx] = val;
}

// ---------------------------------------------------------------------------
// LayerNorm (SPLIT=1: write bf16 hi/lo; SPLIT=0: write fp32)
// ---------------------------------------------------------------------------
__device__ __forceinline__ float block_reduce_sum(float v) {
    __shared__ float sm[8];
    int lane = threadIdx.x & 31;
    int warp = threadIdx.x >> 5;
#pragma unroll
    for (int o = 16; o; o >>= 1) v += __shfl_xor_sync(0xffffffffu, v, o);
    if (lane == 0) sm[warp] = v;
    __syncthreads();
    if (warp == 0) {
        v = (lane < 8) ? sm[lane] : 0.0f;
#pragma unroll
        for (int o = 4; o; o >>= 1) v += __shfl_xor_sync(0xffffffffu, v, o);
        if (lane == 0) sm[0] = v;
    }
    __syncthreads();
    float r = sm[0];
    __syncthreads();
    return r;
}

template <int SPLIT>
__global__ void ln_kernel(const float* __restrict__ in,
                          const float* __restrict__ scale,
                          const float* __restrict__ bias,
                          float* __restrict__ outf,
                          __nv_bfloat16* __restrict__ oh,
                          __nv_bfloat16* __restrict__ ol) {
    int row = blockIdx.x;
    float4 v = ((const float4*)(in + row * DM))[threadIdx.x];
    float mu = block_reduce_sum(v.x + v.y + v.z + v.w) * (1.0f / DM);
    float dx = v.x - mu, dy = v.y - mu, dz = v.z - mu, dw = v.w - mu;
    float var = block_reduce_sum(dx * dx + dy * dy + dz * dz + dw * dw) * (1.0f / DM);
    float rs = rsqrtf(var + 1e-6f);
    float4 s4 = ((const float4*)scale)[threadIdx.x];
    float4 b4 = ((const float4*)bias)[threadIdx.x];
    float4 o;
    o.x = dx * rs * s4.x + b4.x;
    o.y = dy * rs * s4.y + b4.y;
    o.z = dz * rs * s4.z + b4.z;
    o.w = dw * rs * s4.w + b4.w;
    if (SPLIT) {
        __nv_bfloat16 h0, l0, h1, l1, h2, l2, h3, l3;
        split_bf16(o.x, h0, l0); split_bf16(o.y, h1, l1);
        split_bf16(o.z, h2, l2); split_bf16(o.w, h3, l3);
        size_t base = (size_t)row * DM + threadIdx.x * 4;
        __nv_bfloat162 p0, p1;
        p0.x = h0; p0.y = h1; p1.x = h2; p1.y = h3;
        *(__nv_bfloat162*)(oh + base) = p0;
        *(__nv_bfloat162*)(oh + base + 2) = p1;
        p0.x = l0; p0.y = l1; p1.x = l2; p1.y = l3;
        *(__nv_bfloat162*)(ol + base) = p0;
        *(__nv_bfloat162*)(ol + base + 2) = p1;
    } else {
        ((float4*)(outf + row * DM))[threadIdx.x] = o;
    }
}

// ---------------------------------------------------------------------------
// Sparse attention: 16 queries x 1 head per block, online softmax.
// ---------------------------------------------------------------------------
#define QT 16
#define KC 64
__global__ __launch_bounds__(256) void attn_kernel(
    const float* __restrict__ qkv,
    __nv_bfloat16* __restrict__ ch, __nv_bfloat16* __restrict__ cl) {
    __shared__ float qs[QT * 68];
    __shared__ float kv[KC * 68];
    __shared__ float sb[QT * 65];
    __shared__ float st_m[QT], st_l[QT], st_r[QT];

    const int i0 = blockIdx.x * QT;
    const int h = blockIdx.y;
    const int tid = threadIdx.x;
    const bool gq = (i0 < NG);

    {
        int r = tid >> 4, d = (tid & 15) * 4;
        float4 qv = *(const float4*)(qkv + (size_t)(i0 + r) * (3 * DM) + h * HDIM + d);
        *(float4*)&qs[r * 68 + d] = qv;
    }
    if (tid < QT) { st_m[tid] = -1e30f; st_l[tid] = 0.0f; }

    const int jlo = max(NG, i0 - HALFW);
    const int jhi = min(SQ, i0 + QT - 1 + HALFW + 1);
    const int n = gq ? SQ : (NG + jhi - jlo);

    const int pq = tid >> 4;
    const int pd = (tid & 15) * 4;
    float4 acc = make_float4(0.f, 0.f, 0.f, 0.f);

    const int qb = tid & 7;
    const int kb = (tid >> 3) * 2;
    const int w = tid >> 5, lane = tid & 31;
    __syncthreads();

    for (int t0 = 0; t0 < n; t0 += KC) {
        const int cnt = min(KC, n - t0);
        {
            int r = tid >> 2, doff = (tid & 3) * 16;
            if (r < cnt) {
                int t = t0 + r;
                int j = (gq || t < NG) ? t : (jlo + (t - NG));
                const float* kr = qkv + (size_t)j * (3 * DM) + DM + h * HDIM + doff;
                float* dst = &kv[r * 68 + doff];
                *(float4*)(dst + 0) = *(const float4*)(kr + 0);
                *(float4*)(dst + 4) = *(const float4*)(kr + 4);
                *(float4*)(dst + 8) = *(const float4*)(kr + 8);
                *(float4*)(dst + 12) = *(const float4*)(kr + 12);
            }
        }
        __syncthreads();
        if (kb < cnt) {
            float a00 = 0, a01 = 0, a10 = 0, a11 = 0;
#pragma unroll
            for (int d = 0; d < 64; d += 4) {
                float4 q0 = *(float4*)&qs[qb * 68 + d];
                float4 q1 = *(float4*)&qs[(qb + 8) * 68 + d];
                float4 k0 = *(float4*)&kv[kb * 68 + d];
                float4 k1 = *(float4*)&kv[(kb + 1) * 68 + d];
                a00 += q0.x * k0.x + q0.y * k0.y + q0.z * k0.z + q0.w * k0.w;
                a01 += q0.x * k1.x + q0.y * k1.y + q0.z * k1.z + q0.w * k1.w;
                a10 += q1.x * k0.x + q1.y * k0.y + q1.z * k0.z + q1.w * k0.w;
                a11 += q1.x * k1.x + q1.y * k1.y + q1.z * k1.z + q1.w * k1.w;
            }
            if (gq) {
                sb[qb * 65 + kb] = a00;
                sb[(qb + 8) * 65 + kb] = a10;
                if (kb + 1 < cnt) {
                    sb[qb * 65 + kb + 1] = a01;
                    sb[(qb + 8) * 65 + kb + 1] = a11;
                }
            } else {
                int t = t0 + kb, t1 = t + 1;
                int j0 = (t < NG) ? t : (jlo + (t - NG));
                int j1 = (t1 < NG) ? t1 : (jlo + (t1 - NG));
                int iA = i0 + qb, iB = i0 + qb + 8;
                bool m00 = (j0 < NG) || (abs(iA - j0) <= HALFW);
                bool m10 = (j0 < NG) || (abs(iB - j0) <= HALFW);
                sb[qb * 65 + kb] = m00 ? a00 : -1e9f;
                sb[(qb + 8) * 65 + kb] = m10 ? a10 : -1e9f;
                if (kb + 1 < cnt) {
                    bool m01 = (j1 < NG) || (abs(iA - j1) <= HALFW);
                    bool m11 = (j1 < NG) || (abs(iB - j1) <= HALFW);
                    sb[qb * 65 + kb + 1] = m01 ? a01 : -1e9f;
                    sb[(qb + 8) * 65 + kb + 1] = m11 ? a11 : -1e9f;
                }
            }
        }
        __syncthreads();
        if (w < 8) {
#pragma unroll
            for (int rr = 0; rr < 2; rr++) {
                int r = w + rr * 8;
                float cm = -1e30f;
                for (int t = lane; t < cnt; t += 32) cm = fmaxf(cm, sb[r * 65 + t]);
#pragma unroll
                for (int o = 16; o; o >>= 1)
                    cm = fmaxf(cm, __shfl_xor_sync(0xffffffffu, cm, o));
                float m_old = st_m[r];
                float m_new = fmaxf(m_old, cm);
                float sum = 0.0f;
                for (int t = lane; t < cnt; t += 32) {
                    float e = expf(sb[r * 65 + t] - m_new);
                    sb[r * 65 + t] = e;
                    sum += e;
                }
#pragma unroll
                for (int o = 16; o; o >>= 1) sum += __shfl_xor_sync(0xffffffffu, sum, o);
                if (lane == 0) {
                    float rsc = expf(m_old - m_new);
                    st_r[r] = rsc;
                    st_l[r] = st_l[r] * rsc + sum;
                    st_m[r] = m_new;
                }
            }
        }
        __syncthreads();
        {
            int r = tid >> 2, doff = (tid & 3) * 16;
            if (r < cnt) {
                int t = t0 + r;
                int j = (gq || t < NG) ? t : (jlo + (t - NG));
                const float* vr = qkv + (size_t)j * (3 * DM) + 2 * DM + h * HDIM + doff;
                float* dst = &kv[r * 68 + doff];
                *(float4*)(dst + 0) = *(const float4*)(vr + 0);
                *(float4*)(dst + 4) = *(const float4*)(vr + 4);
                *(float4*)(dst + 8) = *(const float4*)(vr + 8);
                *(float4*)(dst + 12) = *(const float4*)(vr + 12);
            }
        }
        __syncthreads();
        {
            float rsc = st_r[pq];
            acc.x *= rsc; acc.y *= rsc; acc.z *= rsc; acc.w *= rsc;
            for (int kk = 0; kk < cnt; kk++) {
                float p = sb[pq * 65 + kk];
                float4 vv = *(float4*)&kv[kk * 68 + pd];
                acc.x += p * vv.x; acc.y += p * vv.y;
                acc.z += p * vv.z; acc.w += p * vv.w;
            }
        }
        __syncthreads();
    }

    {
        float inv = 1.0f / st_l[pq];
        float o0 = acc.x * inv, o1 = acc.y * inv, o2 = acc.z * inv, o3 = acc.w * inv;
        __nv_bfloat16 h0, l0, h1, l1, h2, l2, h3, l3;
        split_bf16(o0, h0, l0); split_bf16(o1, h1, l1);
        split_bf16(o2, h2, l2); split_bf16(o3, h3, l3);
        size_t base = (size_t)(i0 + pq) * DM + h * HDIM + pd;
        __nv_bfloat162 p0, p1;
        p0.x = h0; p0.y = h1; p1.x = h2; p1.y = h3;
        *(__nv_bfloat162*)(ch + base) = p0;
        *(__nv_bfloat162*)(ch + base + 2) = p1;
        p0.x = l0; p0.y = l1; p1.x = l2; p1.y = l3;
        *(__nv_bfloat162*)(cl + base) = p0;
        *(__nv_bfloat162*)(cl + base + 2) = p1;
    }
}

// ---------------------------------------------------------------------------
// Launch
// ---------------------------------------------------------------------------
extern "C" void kernel_launch(void* const* d_in, const int* in_sizes, int n_in,
                              void* d_out, int out_size) {
    const int* inputs = (const int*)d_in[0];
    const float* embed = (const float*)d_in[2];
    const float* wq = (const float*)d_in[3];
    const float* wk = (const float*)d_in[4];
    const float* wv = (const float*)d_in[5];
    const float* wo = (const float*)d_in[6];
    const float* ln1s = (const float*)d_in[7];
    const float* ln1b = (const float*)d_in[8];
    const float* ln2s = (const float*)d_in[9];
    const float* ln2b = (const float*)d_in[10];
    const float* w1 = (const float*)d_in[11];
    const float* b1 = (const float*)d_in[12];
    const float* w2 = (const float*)d_in[13];
    const float* b2 = (const float*)d_in[14];
    const float* lnfs = (const float*)d_in[15];
    const float* lnfb = (const float*)d_in[16];
    float* out = (float*)d_out;

    float *xp, *qkvp;
    __nv_bfloat16 *hh, *hl, *chp, *clp, *y1h, *y1l;
    __nv_bfloat16 *wqkvh, *wqkvl, *woh, *wol, *w1h, *w1l, *w2h, *w2l;
    cudaGetSymbolAddress((void**)&xp, g_x);
    cudaGetSymbolAddress((void**)&qkvp, g_qkv);
    cudaGetSymbolAddress((void**)&hh, g_hh);
    cudaGetSymbolAddress((void**)&hl, g_hl);
    cudaGetSymbolAddress((void**)&chp, g_ch);
    cudaGetSymbolAddress((void**)&clp, g_cl);
    cudaGetSymbolAddress((void**)&y1h, g_y1h);
    cudaGetSymbolAddress((void**)&y1l, g_y1l);
    cudaGetSymbolAddress((void**)&wqkvh, g_wqkvh);
    cudaGetSymbolAddress((void**)&wqkvl, g_wqkvl);
    cudaGetSymbolAddress((void**)&woh, g_woh);
    cudaGetSymbolAddress((void**)&wol, g_wol);
    cudaGetSymbolAddress((void**)&w1h, g_w1h);
    cudaGetSymbolAddress((void**)&w1l, g_w1l);
    cudaGetSymbolAddress((void**)&w2h, g_w2h);
    cudaGetSymbolAddress((void**)&w2l, g_w2l);

    cudaFuncSetAttribute(mma_gemm<0, 0, 0, 0>, cudaFuncAttributeMaxDynamicSharedMemorySize, DYNSM);
    cudaFuncSetAttribute(mma_gemm<0, 0, 1, 0>, cudaFuncAttributeMaxDynamicSharedMemorySize, DYNSM);
    cudaFuncSetAttribute(mma_gemm<1, 1, 0, 1>, cudaFuncAttributeMaxDynamicSharedMemorySize, DYNSM);
    cudaFuncSetAttribute(mma_gemm<1, 0, 1, 0>, cudaFuncAttributeMaxDynamicSharedMemorySize, DYNSM);

    const long WA = (long)DM * DM;
    const long WM = (long)DM * MLPD;
    dim3 tb(32, 8);
    transpose_split<<<dim3(32, 32, NL), tb>>>(wq, wqkvh, wqkvl, DM, DM, 0.125f, WA, 3 * WA);
    transpose_split<<<dim3(32, 32, NL), tb>>>(wk, wqkvh + WA, wqkvl + WA, DM, DM, 1.0f, WA, 3 * WA);
    transpose_split<<<dim3(32, 32, NL), tb>>>(wv, wqkvh + 2 * WA, wqkvl + 2 * WA, DM, DM, 1.0f, WA, 3 * WA);
    transpose_split<<<dim3(32, 32, NL), tb>>>(wo, woh, wol, DM, DM, 1.0f, WA, WA);
    transpose_split<<<dim3(MLPD / 32, DM / 32, NL), tb>>>(w1, w1h, w1l, DM, MLPD, 1.0f, WM, WM);
    transpose_split<<<dim3(DM / 32, MLPD / 32, NL), tb>>>(w2, w2h, w2l, MLPD, DM, 1.0f, WM, WM);

    embed_kernel<<<SQ * DM / 256, 256>>>(inputs, embed);

    dim3 g_qkvg(3 * DM / 128, SQ / 128);
    dim3 g_1024(DM / 128, SQ / 128);
    dim3 g_4096(MLPD / 128, SQ / 128);

    for (int l = 0; l < NL; l++) {
        ln_kernel<1><<<SQ, 256>>>(xp, ln1s + l * DM, ln1b + l * DM, nullptr, hh, hl);

        mma_gemm<0, 0, 0, 0><<<g_qkvg, 256, DYNSM>>>(
            hh, hl, wqkvh + (size_t)l * 3 * WA, wqkvl + (size_t)l * 3 * WA,
            nullptr, nullptr, qkvp, nullptr, nullptr, DM, 3 * DM);

        attn_kernel<<<dim3(SQ / QT, NH), 256>>>(qkvp, chp, clp);

        mma_gemm<0, 0, 1, 0><<<g_1024, 256, DYNSM>>>(
            chp, clp, woh + (size_t)l * WA, wol + (size_t)l * WA,
            nullptr, xp, xp, nullptr, nullptr, DM, DM);

        ln_kernel<1><<<SQ, 256>>>(xp, ln2s + l * DM, ln2b + l * DM, nullptr, hh, hl);

        mma_gemm<1, 1, 0, 1><<<g_4096, 256, DYNSM>>>(
            hh, hl, w1h + (size_t)l * WM, w1l + (size_t)l * WM,
            b1 + l * MLPD, nullptr, nullptr, y1h, y1l, DM, MLPD);

        mma_gemm<1, 0, 1, 0><<<g_1024, 256, DYNSM>>>(
            y1h, y1l, w2h + (size_t)l * WM, w2l + (size_t)l * WM,
            b2 + l * DM, xp, xp, nullptr, nullptr, MLPD, DM);
    }

    ln_kernel<0><<<SQ, 256>>>(xp, lnfs, lnfb, out, nullptr, nullptr);
}

// round 11
// speedup vs baseline: 1.7625x; 1.1008x over previous
#include <cuda_runtime.h>
#include <cuda_fp16.h>
#include <math.h>
#include <stdint.h>

#define SQ   2048
#define DM   1024
#define NH   16
#define HDIM 64
#define MLPD 4096
#define NL   4
#define HALFW 256
#define NG   64

// ---------------- scratch (device globals; no allocation allowed) ----------
__device__ float g_x[SQ * DM];            // residual stream (fp32)
__device__ float g_qkv[SQ * 3 * DM];      // fused qkv output (fp32)
__device__ __half g_hh[SQ * DM];          // LN out (fp16)
__device__ __half g_ch[SQ * DM];          // ctx (fp16)
__device__ __half g_y1h[SQ * MLPD];       // mlp mid (fp16)
__device__ __half g_wqkvh[NL * 3 * DM * DM];
__device__ __half g_wqkvl[NL * 3 * DM * DM];
__device__ __half g_woh[NL * DM * DM];
__device__ __half g_wol[NL * DM * DM];
__device__ __half g_w1h[NL * DM * MLPD];
__device__ __half g_w1l[NL * DM * MLPD];
__device__ __half g_w2h[NL * MLPD * DM];
__device__ __half g_w2l[NL * MLPD * DM];

// ---------------- helpers ---------------------------------------------------
__device__ __forceinline__ uint32_t smem_u32(const void* p) {
    uint32_t a;
    asm("{ .reg .u64 t; cvta.to.shared.u64 t, %1; cvt.u32.u64 %0, t; }"
        : "=r"(a) : "l"(p));
    return a;
}

__device__ __forceinline__ void ldsm4(uint32_t* r, uint32_t addr) {
    asm volatile("ldmatrix.sync.aligned.m8n8.x4.shared.b16 {%0,%1,%2,%3}, [%4];"
                 : "=r"(r[0]), "=r"(r[1]), "=r"(r[2]), "=r"(r[3]) : "r"(addr));
}

__device__ __forceinline__ void mma_f16(float* c, const uint32_t* a,
                                        const uint32_t* b) {
    asm volatile(
        "mma.sync.aligned.m16n8k16.row.col.f32.f16.f16.f32 "
        "{%0,%1,%2,%3}, {%4,%5,%6,%7}, {%8,%9}, {%0,%1,%2,%3};"
        : "+f"(c[0]), "+f"(c[1]), "+f"(c[2]), "+f"(c[3])
        : "r"(a[0]), "r"(a[1]), "r"(a[2]), "r"(a[3]), "r"(b[0]), "r"(b[1]));
}

#define CP16(dst, src) \
    asm volatile("cp.async.ca.shared.global [%0], [%1], 16;" ::"r"(dst), "l"(src) : "memory")
#define CPCOMMIT() asm volatile("cp.async.commit_group;" ::: "memory")

__device__ __forceinline__ void split_f16(float v, __half& h, __half& l) {
    h = __float2half_rn(v);
    l = __float2half_rn(v - __half2float(h));
}

// smem geometry (bytes): swizzled, no padding.
// Row = 32 fp16 = 64B = 4 x 16B groups; phys group = logical ^ ((row>>1)&3).
#define ROWB  64
#define PART  (128 * ROWB)   // 8192 B
#define BUFB  (3 * PART)     // 24576 B: A, Bh, Bl
#define DYNSM (2 * BUFB + 128)

__device__ __forceinline__ uint32_t swz(uint32_t row, uint32_t g16) {
    return row * ROWB + ((g16 ^ ((row >> 1) & 3u)) << 4);
}

// ---------------------------------------------------------------------------
// fp16 2-term GEMM: C[M,N] = epi(A[M,K] @ (Bh+Bl)[N,K]^T)
// A fp16 (rounded activations), Bh/Bl fp16 (split weights).
// 128x128x32 tile, 256 thr, 2 CTAs/SM, cp.async 2 chunks deep.
// ---------------------------------------------------------------------------
template <int BIAS, int RELU, int RESID, int OHALF>
__global__ __launch_bounds__(256, 2) void mma_gemm(
    const __half* __restrict__ A,
    const __half* __restrict__ Bh, const __half* __restrict__ Bl,
    const float* __restrict__ bias, const float* __restrict__ resid,
    float* __restrict__ Cf, __half* __restrict__ Co, int K, int N) {
    extern __shared__ __align__(16) char dsm[];
    const uint32_t sbase = (smem_u32(dsm) + 127u) & ~127u;

    const int tid = threadIdx.x;
    const int wid = tid >> 5, lane = tid & 31;
    const int srow = tid >> 1, sseg = tid & 1;

    const __half* pA = A + ((size_t)blockIdx.y * 128 + srow) * (size_t)K;
    const __half* pBh = Bh + ((size_t)blockIdx.x * 128 + srow) * (size_t)K;
    const __half* pBl = Bl + ((size_t)blockIdx.x * 128 + srow) * (size_t)K;

    float acc[4][4][4];
#pragma unroll
    for (int i = 0; i < 4; i++)
#pragma unroll
        for (int j = 0; j < 4; j++)
#pragma unroll
            for (int f = 0; f < 4; f++) acc[i][j][f] = 0.0f;

    const uint32_t dA = swz((uint32_t)srow, (uint32_t)(2 * sseg));
    const uint32_t dB = swz((uint32_t)srow, (uint32_t)(2 * sseg + 1));
    const int CH = K >> 5;

#define ISSUE(c)                                                        \
    {                                                                   \
        uint32_t b = sbase + (uint32_t)((c) & 1) * BUFB;                \
        size_t off = (size_t)(c) * 32 + sseg * 16;                      \
        CP16(b + dA, pA + off);                                         \
        CP16(b + dB, pA + off + 8);                                     \
        CP16(b + PART + dA, pBh + off);                                 \
        CP16(b + PART + dB, pBh + off + 8);                             \
        CP16(b + 2 * PART + dA, pBl + off);                             \
        CP16(b + 2 * PART + dB, pBl + off + 8);                         \
        CPCOMMIT();                                                     \
    }

    ISSUE(0);
    ISSUE(1);

    const int m_base = (wid & 1) * 64;
    const int n_base = (wid >> 1) * 32;
    const int lgrp = lane >> 3, lr = lane & 7;

    for (int c = 0; c < CH; c++) {
        if (c + 1 < CH) {
            asm volatile("cp.async.wait_group 1;" ::: "memory");
        } else {
            asm volatile("cp.async.wait_group 0;" ::: "memory");
        }
        __syncthreads();

        const uint32_t sb0 = sbase + (uint32_t)(c & 1) * BUFB;
#pragma unroll
        for (int ks = 0; ks < 2; ks++) {
            uint32_t bh[4][2], bl[4][2];
#pragma unroll
            for (int p = 0; p < 2; p++) {
                uint32_t row = (uint32_t)(n_base + p * 16 + (lgrp >> 1) * 8 + lr);
                uint32_t ad = sb0 + PART + swz(row, (uint32_t)(ks * 2 + (lgrp & 1)));
                uint32_t t[4];
                ldsm4(t, ad);
                bh[2 * p][0] = t[0]; bh[2 * p][1] = t[1];
                bh[2 * p + 1][0] = t[2]; bh[2 * p + 1][1] = t[3];
                ldsm4(t, ad + PART);
                bl[2 * p][0] = t[0]; bl[2 * p][1] = t[1];
                bl[2 * p + 1][0] = t[2]; bl[2 * p + 1][1] = t[3];
            }
#pragma unroll
            for (int mt = 0; mt < 4; mt++) {
                uint32_t row = (uint32_t)(m_base + mt * 16 + (lgrp & 1) * 8 + lr);
                uint32_t ad = sb0 + swz(row, (uint32_t)(ks * 2 + (lgrp >> 1)));
                uint32_t ah[4];
                ldsm4(ah, ad);
#pragma unroll
                for (int nt = 0; nt < 4; nt++) {
                    mma_f16(acc[mt][nt], ah, bh[nt]);
                    mma_f16(acc[mt][nt], ah, bl[nt]);
                }
            }
        }
        __syncthreads();
        if (c + 2 < CH) ISSUE(c + 2);
    }

    // epilogue
    const int m0 = blockIdx.y * 128 + m_base;
    const int n0 = blockIdx.x * 128 + n_base;
    const int mr = lane >> 2, nc = (lane & 3) * 2;
#pragma unroll
    for (int mt = 0; mt < 4; mt++) {
#pragma unroll
        for (int half = 0; half < 2; half++) {
            const size_t m = (size_t)(m0 + mt * 16 + mr + half * 8);
#pragma unroll
            for (int nt = 0; nt < 4; nt++) {
                const int n = n0 + nt * 8 + nc;
                float v0 = acc[mt][nt][2 * half];
                float v1 = acc[mt][nt][2 * half + 1];
                if (BIAS) { v0 += bias[n]; v1 += bias[n + 1]; }
                if (RELU) { v0 = fmaxf(v0, 0.0f); v1 = fmaxf(v1, 0.0f); }
                if (RESID) {
                    float2 r2 = *(const float2*)(resid + m * N + n);
                    v0 += r2.x; v1 += r2.y;
                }
                if (OHALF) {
                    *(__half2*)(Co + m * N + n) = __floats2half2_rn(v0, v1);
                } else {
                    float2 o; o.x = v0; o.y = v1;
                    *(float2*)(Cf + m * N + n) = o;
                }
            }
        }
    }
}

// ---------------------------------------------------------------------------
// Batched weight transpose + fp16 split. One launch for all 6 weight groups.
// Flat block ranges: [0,16384) att (4 tensors x 4 layers x 1024 tiles),
// [16384,32768) w1, [32768,49152) w2.
// ---------------------------------------------------------------------------
__global__ void transpose_all(
    const float* __restrict__ wq, const float* __restrict__ wk,
    const float* __restrict__ wv, const float* __restrict__ wo,
    const float* __restrict__ w1, const float* __restrict__ w2,
    __half* __restrict__ wqkvh, __half* __restrict__ wqkvl,
    __half* __restrict__ woh, __half* __restrict__ wol,
    __half* __restrict__ w1h, __half* __restrict__ w1l,
    __half* __restrict__ w2h, __half* __restrict__ w2l) {
    const long WA = (long)DM * DM;
    const long WM = (long)DM * MLPD;
    int g = blockIdx.x;
    const float* in;
    __half *oh, *ol;
    int R, C, cx, ry, l;
    float alpha = 1.0f;
    if (g < 16384) {
        int tensor = g >> 12;         // 0..3 (q,k,v,o)
        int gg = g & 4095;
        l = gg >> 10;
        int t = gg & 1023;
        R = DM; C = DM;
        cx = t & 31; ry = t >> 5;
        if (tensor == 0) {
            in = wq + l * WA; oh = wqkvh + (size_t)l * 3 * WA; ol = wqkvl + (size_t)l * 3 * WA;
            alpha = 0.125f;
        } else if (tensor == 1) {
            in = wk + l * WA; oh = wqkvh + (size_t)l * 3 * WA + WA; ol = wqkvl + (size_t)l * 3 * WA + WA;
        } else if (tensor == 2) {
            in = wv + l * WA; oh = wqkvh + (size_t)l * 3 * WA + 2 * WA; ol = wqkvl + (size_t)l * 3 * WA + 2 * WA;
        } else {
            in = wo + l * WA; oh = woh + (size_t)l * WA; ol = wol + (size_t)l * WA;
        }
    } else if (g < 32768) {
        int gg = g - 16384;
        l = gg >> 12;
        int t = gg & 4095;
        R = DM; C = MLPD;
        cx = t & 127; ry = t >> 7;
        in = w1 + (size_t)l * WM; oh = w1h + (size_t)l * WM; ol = w1l + (size_t)l * WM;
    } else {
        int gg = g - 32768;
        l = gg >> 12;
        int t = gg & 4095;
        R = MLPD; C = DM;
        cx = t & 31; ry = t >> 5;
        in = w2 + (size_t)l * WM; oh = w2h + (size_t)l * WM; ol = w2l + (size_t)l * WM;
    }
    __shared__ float tbuf[32][33];
    const int c0 = cx * 32, r0 = ry * 32;
    for (int k = threadIdx.y; k < 32; k += 8)
        tbuf[k][threadIdx.x] = in[(size_t)(r0 + k) * C + c0 + threadIdx.x] * alpha;
    __syncthreads();
    for (int k = threadIdx.y; k < 32; k += 8) {
        float v = tbuf[threadIdx.x][k];
        __half hv, lv;
        split_f16(v, hv, lv);
        size_t o = (size_t)(c0 + k) * R + r0 + threadIdx.x;
        oh[o] = hv;
        ol[o] = lv;
    }
}

// ---------------------------------------------------------------------------
// Embedding + sinusoidal positional encoding
// ---------------------------------------------------------------------------
__global__ void embed_kernel(const int* __restrict__ inputs,
                             const float* __restrict__ emb) {
    int idx = blockIdx.x * blockDim.x + threadIdx.x;
    int s = idx >> 10;
    int d = idx & 1023;
    int tok = inputs[s];
    float val = emb[tok * DM + d];
    int k2 = d >> 1;
    float div = expf((float)(2 * k2) * (-9.210340371976184f / 1024.0f));
    float ang = (float)s * div;
    val += (d & 1) ? cosf(ang) : sinf(ang);
    g_x[idx] = val;
}

// ---------------------------------------------------------------------------
// LayerNorm (HALF=1: write fp16; HALF=0: write fp32)
// ---------------------------------------------------------------------------
__device__ __forceinline__ float block_reduce_sum(float v) {
    __shared__ float sm[8];
    int lane = threadIdx.x & 31;
    int warp = threadIdx.x >> 5;
#pragma unroll
    for (int o = 16; o; o >>= 1) v += __shfl_xor_sync(0xffffffffu, v, o);
    if (lane == 0) sm[warp] = v;
    __syncthreads();
    if (warp == 0) {
        v = (lane < 8) ? sm[lane] : 0.0f;
#pragma unroll
        for (int o = 4; o; o >>= 1) v += __shfl_xor_sync(0xffffffffu, v, o);
        if (lane == 0) sm[0] = v;
    }
    __syncthreads();
    float r = sm[0];
    __syncthreads();
    return r;
}

template <int HALF>
__global__ void ln_kernel(const float* __restrict__ in,
                          const float* __restrict__ scale,
                          const float* __restrict__ bias,
                          float* __restrict__ outf,
                          __half* __restrict__ oh) {
    int row = blockIdx.x;
    float4 v = ((const float4*)(in + row * DM))[threadIdx.x];
    float mu = block_reduce_sum(v.x + v.y + v.z + v.w) * (1.0f / DM);
    float dx = v.x - mu, dy = v.y - mu, dz = v.z - mu, dw = v.w - mu;
    float var = block_reduce_sum(dx * dx + dy * dy + dz * dz + dw * dw) * (1.0f / DM);
    float rs = rsqrtf(var + 1e-6f);
    float4 s4 = ((const float4*)scale)[threadIdx.x];
    float4 b4 = ((const float4*)bias)[threadIdx.x];
    float4 o;
    o.x = dx * rs * s4.x + b4.x;
    o.y = dy * rs * s4.y + b4.y;
    o.z = dz * rs * s4.z + b4.z;
    o.w = dw * rs * s4.w + b4.w;
    if (HALF) {
        size_t base = (size_t)row * DM + threadIdx.x * 4;
        *(__half2*)(oh + base) = __floats2half2_rn(o.x, o.y);
        *(__half2*)(oh + base + 2) = __floats2half2_rn(o.z, o.w);
    } else {
        ((float4*)(outf + row * DM))[threadIdx.x] = o;
    }
}

// ---------------------------------------------------------------------------
// Sparse attention: 16 queries x 1 head per block, online softmax.
// ---------------------------------------------------------------------------
#define QT 16
#define KC 64
__global__ __launch_bounds__(256) void attn_kernel(
    const float* __restrict__ qkv, __half* __restrict__ ch) {
    __shared__ float qs[QT * 68];
    __shared__ float kv[KC * 68];
    __shared__ float sb[QT * 65];
    __shared__ float st_m[QT], st_l[QT], st_r[QT];

    const int i0 = blockIdx.x * QT;
    const int h = blockIdx.y;
    const int tid = threadIdx.x;
    const bool gq = (i0 < NG);

    {
        int r = tid >> 4, d = (tid & 15) * 4;
        float4 qv = *(const float4*)(qkv + (size_t)(i0 + r) * (3 * DM) + h * HDIM + d);
        *(float4*)&qs[r * 68 + d] = qv;
    }
    if (tid < QT) { st_m[tid] = -1e30f; st_l[tid] = 0.0f; }

    const int jlo = max(NG, i0 - HALFW);
    const int jhi = min(SQ, i0 + QT - 1 + HALFW + 1);
    const int n = gq ? SQ : (NG + jhi - jlo);

    const int pq = tid >> 4;
    const int pd = (tid & 15) * 4;
    float4 acc = make_float4(0.f, 0.f, 0.f, 0.f);

    const int qb = tid & 7;
    const int kb = (tid >> 3) * 2;
    const int w = tid >> 5, lane = tid & 31;
    __syncthreads();

    for (int t0 = 0; t0 < n; t0 += KC) {
        const int cnt = min(KC, n - t0);
        {
            int r = tid >> 2, doff = (tid & 3) * 16;
            if (r < cnt) {
                int t = t0 + r;
                int j = (gq || t < NG) ? t : (jlo + (t - NG));
                const float* kr = qkv + (size_t)j * (3 * DM) + DM + h * HDIM + doff;
                float* dst = &kv[r * 68 + doff];
                *(float4*)(dst + 0) = *(const float4*)(kr + 0);
                *(float4*)(dst + 4) = *(const float4*)(kr + 4);
                *(float4*)(dst + 8) = *(const float4*)(kr + 8);
                *(float4*)(dst + 12) = *(const float4*)(kr + 12);
            }
        }
        __syncthreads();
        if (kb < cnt) {
            float a00 = 0, a01 = 0, a10 = 0, a11 = 0;
#pragma unroll
            for (int d = 0; d < 64; d += 4) {
                float4 q0 = *(float4*)&qs[qb * 68 + d];
                float4 q1 = *(float4*)&qs[(qb + 8) * 68 + d];
                float4 k0 = *(float4*)&kv[kb * 68 + d];
                float4 k1 = *(float4*)&kv[(kb + 1) * 68 + d];
                a00 += q0.x * k0.x + q0.y * k0.y + q0.z * k0.z + q0.w * k0.w;
                a01 += q0.x * k1.x + q0.y * k1.y + q0.z * k1.z + q0.w * k1.w;
                a10 += q1.x * k0.x + q1.y * k0.y + q1.z * k0.z + q1.w * k0.w;
                a11 += q1.x * k1.x + q1.y * k1.y + q1.z * k1.z + q1.w * k1.w;
            }
            if (gq) {
                sb[qb * 65 + kb] = a00;
                sb[(qb + 8) * 65 + kb] = a10;
                if (kb + 1 < cnt) {
                    sb[qb * 65 + kb + 1] = a01;
                    sb[(qb + 8) * 65 + kb + 1] = a11;
                }
            } else {
                int t = t0 + kb, t1 = t + 1;
                int j0 = (t < NG) ? t : (jlo + (t - NG));
                int j1 = (t1 < NG) ? t1 : (jlo + (t1 - NG));
                int iA = i0 + qb, iB = i0 + qb + 8;
                bool m00 = (j0 < NG) || (abs(iA - j0) <= HALFW);
                bool m10 = (j0 < NG) || (abs(iB - j0) <= HALFW);
                sb[qb * 65 + kb] = m00 ? a00 : -1e9f;
                sb[(qb + 8) * 65 + kb] = m10 ? a10 : -1e9f;
                if (kb + 1 < cnt) {
                    bool m01 = (j1 < NG) || (abs(iA - j1) <= HALFW);
                    bool m11 = (j1 < NG) || (abs(iB - j1) <= HALFW);
                    sb[qb * 65 + kb + 1] = m01 ? a01 : -1e9f;
                    sb[(qb + 8) * 65 + kb + 1] = m11 ? a11 : -1e9f;
                }
            }
        }
        __syncthreads();
        if (w < 8) {
#pragma unroll
            for (int rr = 0; rr < 2; rr++) {
                int r = w + rr * 8;
                float cm = -1e30f;
                for (int t = lane; t < cnt; t += 32) cm = fmaxf(cm, sb[r * 65 + t]);
#pragma unroll
                for (int o = 16; o; o >>= 1)
                    cm = fmaxf(cm, __shfl_xor_sync(0xffffffffu, cm, o));
                float m_old = st_m[r];
                float m_new = fmaxf(m_old, cm);
                float sum = 0.0f;
                for (int t = lane; t < cnt; t += 32) {
                    float e = expf(sb[r * 65 + t] - m_new);
                    sb[r * 65 + t] = e;
                    sum += e;
                }
#pragma unroll
                for (int o = 16; o; o >>= 1) sum += __shfl_xor_sync(0xffffffffu, sum, o);
                if (lane == 0) {
                    float rsc = expf(m_old - m_new);
                    st_r[r] = rsc;
                    st_l[r] = st_l[r] * rsc + sum;
                    st_m[r] = m_new;
                }
            }
        }
        __syncthreads();
        {
            int r = tid >> 2, doff = (tid & 3) * 16;
            if (r < cnt) {
                int t = t0 + r;
                int j = (gq || t < NG) ? t : (jlo + (t - NG));
                const float* vr = qkv + (size_t)j * (3 * DM) + 2 * DM + h * HDIM + doff;
                float* dst = &kv[r * 68 + doff];
                *(float4*)(dst + 0) = *(const float4*)(vr + 0);
                *(float4*)(dst + 4) = *(const float4*)(vr + 4);
                *(float4*)(dst + 8) = *(const float4*)(vr + 8);
                *(float4*)(dst + 12) = *(const float4*)(vr + 12);
            }
        }
        __syncthreads();
        {
            float rsc = st_r[pq];
            acc.x *= rsc; acc.y *= rsc; acc.z *= rsc; acc.w *= rsc;
            for (int kk = 0; kk < cnt; kk++) {
                float p = sb[pq * 65 + kk];
                float4 vv = *(float4*)&kv[kk * 68 + pd];
                acc.x += p * vv.x; acc.y += p * vv.y;
                acc.z += p * vv.z; acc.w += p * vv.w;
            }
        }
        __syncthreads();
    }

    {
        float inv = 1.0f / st_l[pq];
        size_t base = (size_t)(i0 + pq) * DM + h * HDIM + pd;
        *(__half2*)(ch + base) = __floats2half2_rn(acc.x * inv, acc.y * inv);
        *(__half2*)(ch + base + 2) = __floats2half2_rn(acc.z * inv, acc.w * inv);
    }
}

// ---------------------------------------------------------------------------
// Launch
// ---------------------------------------------------------------------------
extern "C" void kernel_launch(void* const* d_in, const int* in_sizes, int n_in,
                              void* d_out, int out_size) {
    const int* inputs = (const int*)d_in[0];
    const float* embed = (const float*)d_in[2];
    const float* wq = (const float*)d_in[3];
    const float* wk = (const float*)d_in[4];
    const float* wv = (const float*)d_in[5];
    const float* wo = (const float*)d_in[6];
    const float* ln1s = (const float*)d_in[7];
    const float* ln1b = (const float*)d_in[8];
    const float* ln2s = (const float*)d_in[9];
    const float* ln2b = (const float*)d_in[10];
    const float* w1 = (const float*)d_in[11];
    const float* b1 = (const float*)d_in[12];
    const float* w2 = (const float*)d_in[13];
    const float* b2 = (const float*)d_in[14];
    const float* lnfs = (const float*)d_in[15];
    const float* lnfb = (const float*)d_in[16];
    float* out = (float*)d_out;

    float *xp, *qkvp;
    __half *hh, *chp, *y1h;
    __half *wqkvh, *wqkvl, *woh, *wol, *w1h, *w1l, *w2h, *w2l;
    cudaGetSymbolAddress((void**)&xp, g_x);
    cudaGetSymbolAddress((void**)&qkvp, g_qkv);
    cudaGetSymbolAddress((void**)&hh, g_hh);
    cudaGetSymbolAddress((void**)&chp, g_ch);
    cudaGetSymbolAddress((void**)&y1h, g_y1h);
    cudaGetSymbolAddress((void**)&wqkvh, g_wqkvh);
    cudaGetSymbolAddress((void**)&wqkvl, g_wqkvl);
    cudaGetSymbolAddress((void**)&woh, g_woh);
    cudaGetSymbolAddress((void**)&wol, g_wol);
    cudaGetSymbolAddress((void**)&w1h, g_w1h);
    cudaGetSymbolAddress((void**)&w1l, g_w1l);
    cudaGetSymbolAddress((void**)&w2h, g_w2h);
    cudaGetSymbolAddress((void**)&w2l, g_w2l);

    cudaFuncSetAttribute(mma_gemm<0, 0, 0, 0>, cudaFuncAttributeMaxDynamicSharedMemorySize, DYNSM);
    cudaFuncSetAttribute(mma_gemm<0, 0, 1, 0>, cudaFuncAttributeMaxDynamicSharedMemorySize, DYNSM);
    cudaFuncSetAttribute(mma_gemm<1, 1, 0, 1>, cudaFuncAttributeMaxDynamicSharedMemorySize, DYNSM);
    cudaFuncSetAttribute(mma_gemm<1, 0, 1, 0>, cudaFuncAttributeMaxDynamicSharedMemorySize, DYNSM);

    const long WA = (long)DM * DM;
    const long WM = (long)DM * MLPD;

    // launch 0: all weight transposes (one kernel -> launch #5 is a GEMM for ncu)
    transpose_all<<<49152, dim3(32, 8)>>>(wq, wk, wv, wo, w1, w2,
                                          wqkvh, wqkvl, woh, wol,
                                          w1h, w1l, w2h, w2l);
    // launch 1
    embed_kernel<<<SQ * DM / 256, 256>>>(inputs, embed);

    dim3 g_qkvg(3 * DM / 128, SQ / 128);
    dim3 g_1024(DM / 128, SQ / 128);
    dim3 g_4096(MLPD / 128, SQ / 128);

    for (int l = 0; l < NL; l++) {
        ln_kernel<1><<<SQ, 256>>>(xp, ln1s + l * DM, ln1b + l * DM, nullptr, hh);

        mma_gemm<0, 0, 0, 0><<<g_qkvg, 256, DYNSM>>>(
            hh, wqkvh + (size_t)l * 3 * WA, wqkvl + (size_t)l * 3 * WA,
            nullptr, nullptr, qkvp, nullptr, DM, 3 * DM);

        attn_kernel<<<dim3(SQ / QT, NH), 256>>>(qkvp, chp);

        mma_gemm<0, 0, 1, 0><<<g_1024, 256, DYNSM>>>(
            chp, woh + (size_t)l * WA, wol + (size_t)l * WA,
            nullptr, xp, xp, nullptr, DM, DM);

        ln_kernel<1><<<SQ, 256>>>(xp, ln2s + l * DM, ln2b + l * DM, nullptr, hh);

        mma_gemm<1, 1, 0, 1><<<g_4096, 256, DYNSM>>>(
            hh, w1h + (size_t)l * WM, w1l + (size_t)l * WM,
            b1 + l * MLPD, nullptr, nullptr, y1h, DM, MLPD);

        mma_gemm<1, 0, 1, 0><<<g_1024, 256, DYNSM>>>(
            y1h, w2h + (size_t)l * WM, w2l + (size_t)l * WM,
            b2 + l * DM, xp, xp, nullptr, MLPD, DM);
    }

    ln_kernel<0><<<SQ, 256>>>(xp, lnfs, lnfb, out, nullptr);
}

// round 13
// speedup vs baseline: 2.4422x; 1.3856x over previous
#include <cuda_runtime.h>
#include <cuda_fp16.h>
#include <math.h>
#include <stdint.h>

#define SQ   2048
#define DM   1024
#define NH   16
#define HDIM 64
#define MLPD 4096
#define NL   4
#define HALFW 256
#define NG   64

// ---------------- scratch (device globals; no allocation allowed) ----------
__device__ float g_x[SQ * DM];            // residual stream (fp32)
__device__ float g_qkv[SQ * 3 * DM];      // fused qkv output (fp32)
__device__ __half g_hh[SQ * DM];          // LN out (fp16)
__device__ __half g_ch[SQ * DM];          // ctx (fp16)
__device__ __half g_y1h[SQ * MLPD];       // mlp mid (fp16)
__device__ __half g_qh[SQ * DM];          // q rounded fp16
__device__ __half g_kh[SQ * DM];          // k hi
__device__ __half g_kl[SQ * DM];          // k lo
__device__ __half g_vh[SQ * DM];          // v hi
__device__ __half g_vl[SQ * DM];          // v lo
__device__ __half g_wqkvh[NL * 3 * DM * DM];
__device__ __half g_wqkvl[NL * 3 * DM * DM];
__device__ __half g_woh[NL * DM * DM];
__device__ __half g_wol[NL * DM * DM];
__device__ __half g_w1h[NL * DM * MLPD];
__device__ __half g_w1l[NL * DM * MLPD];
__device__ __half g_w2h[NL * MLPD * DM];
__device__ __half g_w2l[NL * MLPD * DM];

// ---------------- helpers ---------------------------------------------------
__device__ __forceinline__ uint32_t smem_u32(const void* p) {
    uint32_t a;
    asm("{ .reg .u64 t; cvta.to.shared.u64 t, %1; cvt.u32.u64 %0, t; }"
        : "=r"(a) : "l"(p));
    return a;
}

__device__ __forceinline__ void ldsm4(uint32_t* r, uint32_t addr) {
    asm volatile("ldmatrix.sync.aligned.m8n8.x4.shared.b16 {%0,%1,%2,%3}, [%4];"
                 : "=r"(r[0]), "=r"(r[1]), "=r"(r[2]), "=r"(r[3]) : "r"(addr));
}

__device__ __forceinline__ void ldsm4t(uint32_t* r, uint32_t addr) {
    asm volatile("ldmatrix.sync.aligned.m8n8.x4.trans.shared.b16 {%0,%1,%2,%3}, [%4];"
                 : "=r"(r[0]), "=r"(r[1]), "=r"(r[2]), "=r"(r[3]) : "r"(addr));
}

__device__ __forceinline__ void mma_f16(float* c, const uint32_t* a,
                                        const uint32_t* b) {
    asm volatile(
        "mma.sync.aligned.m16n8k16.row.col.f32.f16.f16.f32 "
        "{%0,%1,%2,%3}, {%4,%5,%6,%7}, {%8,%9}, {%0,%1,%2,%3};"
        : "+f"(c[0]), "+f"(c[1]), "+f"(c[2]), "+f"(c[3])
        : "r"(a[0]), "r"(a[1]), "r"(a[2]), "r"(a[3]), "r"(b[0]), "r"(b[1]));
}

#define CP16(dst, src) \
    asm volatile("cp.async.ca.shared.global [%0], [%1], 16;" ::"r"(dst), "l"(src) : "memory")
#define CPCOMMIT() asm volatile("cp.async.commit_group;" ::: "memory")

__device__ __forceinline__ void split_f16(float v, __half& h, __half& l) {
    h = __float2half_rn(v);
    l = __float2half_rn(v - __half2float(h));
}

// ---------------- GEMM smem geometry ---------------------------------------
#define ROWB  64
#define PART  (128 * ROWB)   // 8192 B
#define BUFB  (3 * PART)     // 24576 B: A, Bh, Bl
#define DYNSM (2 * BUFB + 128)

__device__ __forceinline__ uint32_t swz(uint32_t row, uint32_t g16) {
    return row * ROWB + ((g16 ^ ((row >> 1) & 3u)) << 4);
}

// ---------------------------------------------------------------------------
// fp16 2-term GEMM: C[M,N] = epi(A[M,K] @ (Bh+Bl)[N,K]^T)
// ---------------------------------------------------------------------------
template <int BIAS, int RELU, int RESID, int OHALF>
__global__ __launch_bounds__(256, 2) void mma_gemm(
    const __half* __restrict__ A,
    const __half* __restrict__ Bh, const __half* __restrict__ Bl,
    const float* __restrict__ bias, const float* __restrict__ resid,
    float* __restrict__ Cf, __half* __restrict__ Co, int K, int N) {
    extern __shared__ __align__(16) char dsm[];
    const uint32_t sbase = (smem_u32(dsm) + 127u) & ~127u;

    const int tid = threadIdx.x;
    const int wid = tid >> 5, lane = tid & 31;
    const int srow = tid >> 1, sseg = tid & 1;

    const __half* pA = A + ((size_t)blockIdx.y * 128 + srow) * (size_t)K;
    const __half* pBh = Bh + ((size_t)blockIdx.x * 128 + srow) * (size_t)K;
    const __half* pBl = Bl + ((size_t)blockIdx.x * 128 + srow) * (size_t)K;

    float acc[4][4][4];
#pragma unroll
    for (int i = 0; i < 4; i++)
#pragma unroll
        for (int j = 0; j < 4; j++)
#pragma unroll
            for (int f = 0; f < 4; f++) acc[i][j][f] = 0.0f;

    const uint32_t dA = swz((uint32_t)srow, (uint32_t)(2 * sseg));
    const uint32_t dB = swz((uint32_t)srow, (uint32_t)(2 * sseg + 1));
    const int CH = K >> 5;

#define ISSUE(c)                                                        \
    {                                                                   \
        uint32_t b = sbase + (uint32_t)((c) & 1) * BUFB;                \
        size_t off = (size_t)(c) * 32 + sseg * 16;                      \
        CP16(b + dA, pA + off);                                         \
        CP16(b + dB, pA + off + 8);                                     \
        CP16(b + PART + dA, pBh + off);                                 \
        CP16(b + PART + dB, pBh + off + 8);                             \
        CP16(b + 2 * PART + dA, pBl + off);                             \
        CP16(b + 2 * PART + dB, pBl + off + 8);                         \
        CPCOMMIT();                                                     \
    }

    ISSUE(0);
    ISSUE(1);

    const int m_base = (wid & 1) * 64;
    const int n_base = (wid >> 1) * 32;
    const int lgrp = lane >> 3, lr = lane & 7;

    for (int c = 0; c < CH; c++) {
        if (c + 1 < CH) {
            asm volatile("cp.async.wait_group 1;" ::: "memory");
        } else {
            asm volatile("cp.async.wait_group 0;" ::: "memory");
        }
        __syncthreads();

        const uint32_t sb0 = sbase + (uint32_t)(c & 1) * BUFB;
#pragma unroll
        for (int ks = 0; ks < 2; ks++) {
            uint32_t bh[4][2], bl[4][2];
#pragma unroll
            for (int p = 0; p < 2; p++) {
                uint32_t row = (uint32_t)(n_base + p * 16 + (lgrp >> 1) * 8 + lr);
                uint32_t ad = sb0 + PART + swz(row, (uint32_t)(ks * 2 + (lgrp & 1)));
                uint32_t t[4];
                ldsm4(t, ad);
                bh[2 * p][0] = t[0]; bh[2 * p][1] = t[1];
                bh[2 * p + 1][0] = t[2]; bh[2 * p + 1][1] = t[3];
                ldsm4(t, ad + PART);
                bl[2 * p][0] = t[0]; bl[2 * p][1] = t[1];
                bl[2 * p + 1][0] = t[2]; bl[2 * p + 1][1] = t[3];
            }
#pragma unroll
            for (int mt = 0; mt < 4; mt++) {
                uint32_t row = (uint32_t)(m_base + mt * 16 + (lgrp & 1) * 8 + lr);
                uint32_t ad = sb0 + swz(row, (uint32_t)(ks * 2 + (lgrp >> 1)));
                uint32_t ah[4];
                ldsm4(ah, ad);
#pragma unroll
                for (int nt = 0; nt < 4; nt++) {
                    mma_f16(acc[mt][nt], ah, bh[nt]);
                    mma_f16(acc[mt][nt], ah, bl[nt]);
                }
            }
        }
        __syncthreads();
        if (c + 2 < CH) ISSUE(c + 2);
    }

    const int m0 = blockIdx.y * 128 + m_base;
    const int n0 = blockIdx.x * 128 + n_base;
    const int mr = lane >> 2, nc = (lane & 3) * 2;
#pragma unroll
    for (int mt = 0; mt < 4; mt++) {
#pragma unroll
        for (int half = 0; half < 2; half++) {
            const size_t m = (size_t)(m0 + mt * 16 + mr + half * 8);
#pragma unroll
            for (int nt = 0; nt < 4; nt++) {
                const int n = n0 + nt * 8 + nc;
                float v0 = acc[mt][nt][2 * half];
                float v1 = acc[mt][nt][2 * half + 1];
                if (BIAS) { v0 += bias[n]; v1 += bias[n + 1]; }
                if (RELU) { v0 = fmaxf(v0, 0.0f); v1 = fmaxf(v1, 0.0f); }
                if (RESID) {
                    float2 r2 = *(const float2*)(resid + m * N + n);
                    v0 += r2.x; v1 += r2.y;
                }
                if (OHALF) {
                    *(__half2*)(Co + m * N + n) = __floats2half2_rn(v0, v1);
                } else {
                    float2 o; o.x = v0; o.y = v1;
                    *(float2*)(Cf + m * N + n) = o;
                }
            }
        }
    }
}

// ---------------------------------------------------------------------------
// Batched weight transpose + fp16 split (one launch for all weights)
// ---------------------------------------------------------------------------
__global__ void transpose_all(
    const float* __restrict__ wq, const float* __restrict__ wk,
    const float* __restrict__ wv, const float* __restrict__ wo,
    const float* __restrict__ w1, const float* __restrict__ w2,
    __half* __restrict__ wqkvh, __half* __restrict__ wqkvl,
    __half* __restrict__ woh, __half* __restrict__ wol,
    __half* __restrict__ w1h, __half* __restrict__ w1l,
    __half* __restrict__ w2h, __half* __restrict__ w2l) {
    const long WA = (long)DM * DM;
    const long WM = (long)DM * MLPD;
    int g = blockIdx.x;
    const float* in;
    __half *oh, *ol;
    int R, C, cx, ry, l;
    float alpha = 1.0f;
    if (g < 16384) {
        int tensor = g >> 12;
        int gg = g & 4095;
        l = gg >> 10;
        int t = gg & 1023;
        R = DM; C = DM;
        cx = t & 31; ry = t >> 5;
        if (tensor == 0) {
            in = wq + l * WA; oh = wqkvh + (size_t)l * 3 * WA; ol = wqkvl + (size_t)l * 3 * WA;
            alpha = 0.125f;
        } else if (tensor == 1) {
            in = wk + l * WA; oh = wqkvh + (size_t)l * 3 * WA + WA; ol = wqkvl + (size_t)l * 3 * WA + WA;
        } else if (tensor == 2) {
            in = wv + l * WA; oh = wqkvh + (size_t)l * 3 * WA + 2 * WA; ol = wqkvl + (size_t)l * 3 * WA + 2 * WA;
        } else {
            in = wo + l * WA; oh = woh + (size_t)l * WA; ol = wol + (size_t)l * WA;
        }
    } else if (g < 32768) {
        int gg = g - 16384;
        l = gg >> 12;
        int t = gg & 4095;
        R = DM; C = MLPD;
        cx = t & 127; ry = t >> 7;
        in = w1 + (size_t)l * WM; oh = w1h + (size_t)l * WM; ol = w1l + (size_t)l * WM;
    } else {
        int gg = g - 32768;
        l = gg >> 12;
        int t = gg & 4095;
        R = MLPD; C = DM;
        cx = t & 31; ry = t >> 5;
        in = w2 + (size_t)l * WM; oh = w2h + (size_t)l * WM; ol = w2l + (size_t)l * WM;
    }
    __shared__ float tbuf[32][33];
    const int c0 = cx * 32, r0 = ry * 32;
    for (int k = threadIdx.y; k < 32; k += 8)
        tbuf[k][threadIdx.x] = in[(size_t)(r0 + k) * C + c0 + threadIdx.x] * alpha;
    __syncthreads();
    for (int k = threadIdx.y; k < 32; k += 8) {
        float v = tbuf[threadIdx.x][k];
        __half hv, lv;
        split_f16(v, hv, lv);
        size_t o = (size_t)(c0 + k) * R + r0 + threadIdx.x;
        oh[o] = hv;
        ol[o] = lv;
    }
}

// ---------------------------------------------------------------------------
// Split fused qkv fp32 -> qh (rounded), kh/kl, vh/vl fp16
// ---------------------------------------------------------------------------
__global__ void split_qkv(const float* __restrict__ qkv,
                          __half* __restrict__ qh,
                          __half* __restrict__ kh, __half* __restrict__ kl,
                          __half* __restrict__ vh, __half* __restrict__ vl) {
    int idx = (blockIdx.x * 256 + threadIdx.x) * 4;   // over SQ*DM
    int s = idx >> 10, d = idx & 1023;
    size_t src = (size_t)s * (3 * DM) + d;
    size_t dst = (size_t)s * DM + d;
    float4 q4 = *(const float4*)(qkv + src);
    *(__half2*)(qh + dst) = __floats2half2_rn(q4.x, q4.y);
    *(__half2*)(qh + dst + 2) = __floats2half2_rn(q4.z, q4.w);
    float4 k4 = *(const float4*)(qkv + src + DM);
    float4 v4 = *(const float4*)(qkv + src + 2 * DM);
    __half h0, l0, h1, l1, h2, l2, h3, l3;
    split_f16(k4.x, h0, l0); split_f16(k4.y, h1, l1);
    split_f16(k4.z, h2, l2); split_f16(k4.w, h3, l3);
    __half2 p;
    p.x = h0; p.y = h1; *(__half2*)(kh + dst) = p;
    p.x = h2; p.y = h3; *(__half2*)(kh + dst + 2) = p;
    p.x = l0; p.y = l1; *(__half2*)(kl + dst) = p;
    p.x = l2; p.y = l3; *(__half2*)(kl + dst + 2) = p;
    split_f16(v4.x, h0, l0); split_f16(v4.y, h1, l1);
    split_f16(v4.z, h2, l2); split_f16(v4.w, h3, l3);
    p.x = h0; p.y = h1; *(__half2*)(vh + dst) = p;
    p.x = h2; p.y = h3; *(__half2*)(vh + dst + 2) = p;
    p.x = l0; p.y = l1; *(__half2*)(vl + dst) = p;
    p.x = l2; p.y = l3; *(__half2*)(vl + dst + 2) = p;
}

// ---------------------------------------------------------------------------
// Embedding + sinusoidal positional encoding
// ---------------------------------------------------------------------------
__global__ void embed_kernel(const int* __restrict__ inputs,
                             const float* __restrict__ emb) {
    int idx = blockIdx.x * blockDim.x + threadIdx.x;
    int s = idx >> 10;
    int d = idx & 1023;
    int tok = inputs[s];
    float val = emb[tok * DM + d];
    int k2 = d >> 1;
    float div = expf((float)(2 * k2) * (-9.210340371976184f / 1024.0f));
    float ang = (float)s * div;
    val += (d & 1) ? cosf(ang) : sinf(ang);
    g_x[idx] = val;
}

// ---------------------------------------------------------------------------
// LayerNorm
// ---------------------------------------------------------------------------
__device__ __forceinline__ float block_reduce_sum(float v) {
    __shared__ float sm[8];
    int lane = threadIdx.x & 31;
    int warp = threadIdx.x >> 5;
#pragma unroll
    for (int o = 16; o; o >>= 1) v += __shfl_xor_sync(0xffffffffu, v, o);
    if (lane == 0) sm[warp] = v;
    __syncthreads();
    if (warp == 0) {
        v = (lane < 8) ? sm[lane] : 0.0f;
#pragma unroll
        for (int o = 4; o; o >>= 1) v += __shfl_xor_sync(0xffffffffu, v, o);
        if (lane == 0) sm[0] = v;
    }
    __syncthreads();
    float r = sm[0];
    __syncthreads();
    return r;
}

template <int HALF>
__global__ void ln_kernel(const float* __restrict__ in,
                          const float* __restrict__ scale,
                          const float* __restrict__ bias,
                          float* __restrict__ outf,
                          __half* __restrict__ oh) {
    int row = blockIdx.x;
    float4 v = ((const float4*)(in + row * DM))[threadIdx.x];
    float mu = block_reduce_sum(v.x + v.y + v.z + v.w) * (1.0f / DM);
    float dx = v.x - mu, dy = v.y - mu, dz = v.z - mu, dw = v.w - mu;
    float var = block_reduce_sum(dx * dx + dy * dy + dz * dz + dw * dw) * (1.0f / DM);
    float rs = rsqrtf(var + 1e-6f);
    float4 s4 = ((const float4*)scale)[threadIdx.x];
    float4 b4 = ((const float4*)bias)[threadIdx.x];
    float4 o;
    o.x = dx * rs * s4.x + b4.x;
    o.y = dy * rs * s4.y + b4.y;
    o.z = dz * rs * s4.z + b4.z;
    o.w = dw * rs * s4.w + b4.w;
    if (HALF) {
        size_t base = (size_t)row * DM + threadIdx.x * 4;
        *(__half2*)(oh + base) = __floats2half2_rn(o.x, o.y);
        *(__half2*)(oh + base + 2) = __floats2half2_rn(o.z, o.w);
    } else {
        ((float4*)(outf + row * DM))[threadIdx.x] = o;
    }
}

// ---------------------------------------------------------------------------
// Tensor-core flash attention: 16 queries x 1 head per block, 128 threads.
// S = Q(16x64) @ K^T via m16n8k16 (K split hi/lo), online softmax fp32,
// O = P(16x64) @ V via m16n8k16 (V split hi/lo, ldmatrix.trans).
// ---------------------------------------------------------------------------
#define ASTR 72   // half units per smem row (144B = 9x16B, conflict-free)
__global__ __launch_bounds__(128) void attn_kernel(
    const __half* __restrict__ qh, const __half* __restrict__ khg,
    const __half* __restrict__ klg, const __half* __restrict__ vhg,
    const __half* __restrict__ vlg, __half* __restrict__ ch) {
    __shared__ __align__(16) __half qsm[16 * ASTR];
    __shared__ __align__(16) __half ksh[64 * ASTR];
    __shared__ __align__(16) __half ksl[64 * ASTR];
    __shared__ __align__(16) __half vsh[64 * ASTR];
    __shared__ __align__(16) __half vsl[64 * ASTR];
    __shared__ float sb[16 * 68];
    __shared__ __align__(16) __half pb[16 * ASTR];
    __shared__ float st_m[16], st_l[16], st_r[16];

    const int i0 = blockIdx.x * 16;
    const int h = blockIdx.y;
    const int tid = threadIdx.x;
    const int w = tid >> 5, lane = tid & 31;
    const int lgrp = lane >> 3, lr = lane & 7;
    const bool gq = (i0 < NG);

    // stage Q (fp16, already scaled by 0.125 via wq)
    {
        int r = tid >> 3, seg = tid & 7;
        uint4 qv = *(const uint4*)(qh + (size_t)(i0 + r) * DM + h * HDIM + seg * 8);
        *(uint4*)&qsm[r * ASTR + seg * 8] = qv;
    }
    if (tid < 16) { st_m[tid] = -1e30f; st_l[tid] = 0.0f; }
    __syncthreads();

    // preload Q a-frags (stationary)
    uint32_t aq[4][4];
    {
        uint32_t qb = smem_u32(qsm);
#pragma unroll
        for (int ks = 0; ks < 4; ks++)
            ldsm4(aq[ks], qb + (uint32_t)((((lgrp & 1) * 8 + lr) * ASTR + ks * 16 + (lgrp >> 1) * 8) * 2));
    }

    const int jlo = max(NG, i0 - HALFW);
    const int jhi = min(SQ, i0 + 15 + HALFW + 1);
    const int n = gq ? SQ : (NG + jhi - jlo);

    float o0[4] = {0, 0, 0, 0}, o1[4] = {0, 0, 0, 0};
    const int key0 = w * 16;
    const uint32_t kshb = smem_u32(ksh), kslb = smem_u32(ksl);
    const uint32_t vshb = smem_u32(vsh), vslb = smem_u32(vsl);
    const uint32_t pbb = smem_u32(pb);
    const int row = lane >> 2, colb = 2 * (lane & 3);

    for (int t0 = 0; t0 < n; t0 += 64) {
        const int cnt = min(64, n - t0);
        // stage K/V chunk: thread r=tid>>1 handles 32 halfs (4x16B) per part
        {
            int r = tid >> 1, sg = (tid & 1) * 32;
            int t = t0 + r;
            uint32_t so = (uint32_t)(r * ASTR + sg);
            if (r < cnt) {
                int j = (gq || t < NG) ? t : (jlo + (t - NG));
                size_t src = (size_t)j * DM + h * HDIM + sg;
#pragma unroll
                for (int u = 0; u < 4; u++) {
                    *(uint4*)&ksh[so + u * 8] = *(const uint4*)(khg + src + u * 8);
                    *(uint4*)&ksl[so + u * 8] = *(const uint4*)(klg + src + u * 8);
                    *(uint4*)&vsh[so + u * 8] = *(const uint4*)(vhg + src + u * 8);
                    *(uint4*)&vsl[so + u * 8] = *(const uint4*)(vlg + src + u * 8);
                }
            } else {
                uint4 z = make_uint4(0, 0, 0, 0);
#pragma unroll
                for (int u = 0; u < 4; u++) {
                    *(uint4*)&ksh[so + u * 8] = z;
                    *(uint4*)&ksl[so + u * 8] = z;
                    *(uint4*)&vsh[so + u * 8] = z;
                    *(uint4*)&vsl[so + u * 8] = z;
                }
            }
        }
        __syncthreads();

        // S = Q @ K^T  (warp w -> keys key0..key0+15)
        float s0[4] = {0, 0, 0, 0}, s1[4] = {0, 0, 0, 0};
#pragma unroll
        for (int ks = 0; ks < 4; ks++) {
            uint32_t off = (uint32_t)(((key0 + (lgrp & 1) * 8 + lr) * ASTR + ks * 16 + (lgrp >> 1) * 8) * 2);
            uint32_t t4[4];
            ldsm4(t4, kshb + off);
            { uint32_t b[2] = {t4[0], t4[2]}; mma_f16(s0, aq[ks], b); }
            { uint32_t b[2] = {t4[1], t4[3]}; mma_f16(s1, aq[ks], b); }
            ldsm4(t4, kslb + off);
            { uint32_t b[2] = {t4[0], t4[2]}; mma_f16(s0, aq[ks], b); }
            { uint32_t b[2] = {t4[1], t4[3]}; mma_f16(s1, aq[ks], b); }
        }

        // store S to sb with mask
#define PUTS(rw, sl, v)                                                        \
        {                                                                      \
            float vv = (v);                                                    \
            if (!gq) {                                                         \
                int t = t0 + (sl);                                             \
                if (t >= NG) {                                                 \
                    int j = jlo + t - NG;                                      \
                    int d = (i0 + (rw)) - j;                                   \
                    if (d < 0) d = -d;                                         \
                    if (d > HALFW) vv = -1e9f;                                 \
                }                                                              \
            }                                                                  \
            sb[(rw) * 68 + (sl)] = vv;                                         \
        }
        PUTS(row, key0 + colb, s0[0]);
        PUTS(row, key0 + colb + 1, s0[1]);
        PUTS(row + 8, key0 + colb, s0[2]);
        PUTS(row + 8, key0 + colb + 1, s0[3]);
        PUTS(row, key0 + 8 + colb, s1[0]);
        PUTS(row, key0 + 8 + colb + 1, s1[1]);
        PUTS(row + 8, key0 + 8 + colb, s1[2]);
        PUTS(row + 8, key0 + 8 + colb + 1, s1[3]);
#undef PUTS
        __syncthreads();

        // online softmax: warp w handles rows 4w..4w+3
#pragma unroll
        for (int rr = 0; rr < 4; rr++) {
            int r = w * 4 + rr;
            float cm = -1e30f;
            for (int t = lane; t < cnt; t += 32) cm = fmaxf(cm, sb[r * 68 + t]);
#pragma unroll
            for (int o = 16; o; o >>= 1)
                cm = fmaxf(cm, __shfl_xor_sync(0xffffffffu, cm, o));
            float m_old = st_m[r];
            float m_new = fmaxf(m_old, cm);
            float sum = 0.0f;
            for (int t = lane; t < 64; t += 32) {
                if (t < cnt) {
                    float e = __expf(sb[r * 68 + t] - m_new);
                    pb[r * ASTR + t] = __float2half(e);
                    sum += e;
                } else {
                    pb[r * ASTR + t] = __float2half(0.0f);
                }
            }
#pragma unroll
            for (int o = 16; o; o >>= 1) sum += __shfl_xor_sync(0xffffffffu, sum, o);
            if (lane == 0) {
                float rsc = __expf(m_old - m_new);
                st_r[r] = rsc;
                st_l[r] = st_l[r] * rsc + sum;
                st_m[r] = m_new;
            }
        }
        __syncthreads();

        // rescale O, then O += P @ V (warp w -> dims key0..key0+15)
        {
            float r0f = st_r[row], r1f = st_r[row + 8];
            o0[0] *= r0f; o0[1] *= r0f; o0[2] *= r1f; o0[3] *= r1f;
            o1[0] *= r0f; o1[1] *= r0f; o1[2] *= r1f; o1[3] *= r1f;
        }
#pragma unroll
        for (int ks = 0; ks < 4; ks++) {
            uint32_t ap[4];
            ldsm4(ap, pbb + (uint32_t)((((lgrp & 1) * 8 + lr) * ASTR + ks * 16 + (lgrp >> 1) * 8) * 2));
            uint32_t voff = (uint32_t)(((ks * 16 + (lgrp & 1) * 8 + lr) * ASTR + key0 + (lgrp >> 1) * 8) * 2);
            uint32_t t4[4];
            ldsm4t(t4, vshb + voff);
            { uint32_t b[2] = {t4[0], t4[1]}; mma_f16(o0, ap, b); }
            { uint32_t b[2] = {t4[2], t4[3]}; mma_f16(o1, ap, b); }
            ldsm4t(t4, vslb + voff);
            { uint32_t b[2] = {t4[0], t4[1]}; mma_f16(o0, ap, b); }
            { uint32_t b[2] = {t4[2], t4[3]}; mma_f16(o1, ap, b); }
        }
        __syncthreads();
    }

    // write ctx (fp16)
    {
        float inv0 = 1.0f / st_l[row], inv1 = 1.0f / st_l[row + 8];
        size_t b0 = (size_t)(i0 + row) * DM + h * HDIM + key0 + colb;
        size_t b1 = (size_t)(i0 + row + 8) * DM + h * HDIM + key0 + colb;
        *(__half2*)(ch + b0) = __floats2half2_rn(o0[0] * inv0, o0[1] * inv0);
        *(__half2*)(ch + b1) = __floats2half2_rn(o0[2] * inv1, o0[3] * inv1);
        *(__half2*)(ch + b0 + 8) = __floats2half2_rn(o1[0] * inv0, o1[1] * inv0);
        *(__half2*)(ch + b1 + 8) = __floats2half2_rn(o1[2] * inv1, o1[3] * inv1);
    }
}

// ---------------------------------------------------------------------------
// Launch
// ---------------------------------------------------------------------------
extern "C" void kernel_launch(void* const* d_in, const int* in_sizes, int n_in,
                              void* d_out, int out_size) {
    const int* inputs = (const int*)d_in[0];
    const float* embed = (const float*)d_in[2];
    const float* wq = (const float*)d_in[3];
    const float* wk = (const float*)d_in[4];
    const float* wv = (const float*)d_in[5];
    const float* wo = (const float*)d_in[6];
    const float* ln1s = (const float*)d_in[7];
    const float* ln1b = (const float*)d_in[8];
    const float* ln2s = (const float*)d_in[9];
    const float* ln2b = (const float*)d_in[10];
    const float* w1 = (const float*)d_in[11];
    const float* b1 = (const float*)d_in[12];
    const float* w2 = (const float*)d_in[13];
    const float* b2 = (const float*)d_in[14];
    const float* lnfs = (const float*)d_in[15];
    const float* lnfb = (const float*)d_in[16];
    float* out = (float*)d_out;

    float *xp, *qkvp;
    __half *hh, *chp, *y1h, *qhp, *khp, *klp, *vhp, *vlp;
    __half *wqkvh, *wqkvl, *woh, *wol, *w1h, *w1l, *w2h, *w2l;
    cudaGetSymbolAddress((void**)&xp, g_x);
    cudaGetSymbolAddress((void**)&qkvp, g_qkv);
    cudaGetSymbolAddress((void**)&hh, g_hh);
    cudaGetSymbolAddress((void**)&chp, g_ch);
    cudaGetSymbolAddress((void**)&y1h, g_y1h);
    cudaGetSymbolAddress((void**)&qhp, g_qh);
    cudaGetSymbolAddress((void**)&khp, g_kh);
    cudaGetSymbolAddress((void**)&klp, g_kl);
    cudaGetSymbolAddress((void**)&vhp, g_vh);
    cudaGetSymbolAddress((void**)&vlp, g_vl);
    cudaGetSymbolAddress((void**)&wqkvh, g_wqkvh);
    cudaGetSymbolAddress((void**)&wqkvl, g_wqkvl);
    cudaGetSymbolAddress((void**)&woh, g_woh);
    cudaGetSymbolAddress((void**)&wol, g_wol);
    cudaGetSymbolAddress((void**)&w1h, g_w1h);
    cudaGetSymbolAddress((void**)&w1l, g_w1l);
    cudaGetSymbolAddress((void**)&w2h, g_w2h);
    cudaGetSymbolAddress((void**)&w2l, g_w2l);

    cudaFuncSetAttribute(mma_gemm<0, 0, 0, 0>, cudaFuncAttributeMaxDynamicSharedMemorySize, DYNSM);
    cudaFuncSetAttribute(mma_gemm<0, 0, 1, 0>, cudaFuncAttributeMaxDynamicSharedMemorySize, DYNSM);
    cudaFuncSetAttribute(mma_gemm<1, 1, 0, 1>, cudaFuncAttributeMaxDynamicSharedMemorySize, DYNSM);
    cudaFuncSetAttribute(mma_gemm<1, 0, 1, 0>, cudaFuncAttributeMaxDynamicSharedMemorySize, DYNSM);

    const long WA = (long)DM * DM;
    const long WM = (long)DM * MLPD;

    transpose_all<<<49152, dim3(32, 8)>>>(wq, wk, wv, wo, w1, w2,
                                          wqkvh, wqkvl, woh, wol,
                                          w1h, w1l, w2h, w2l);
    embed_kernel<<<SQ * DM / 256, 256>>>(inputs, embed);

    dim3 g_qkvg(3 * DM / 128, SQ / 128);
    dim3 g_1024(DM / 128, SQ / 128);
    dim3 g_4096(MLPD / 128, SQ / 128);

    for (int l = 0; l < NL; l++) {
        ln_kernel<1><<<SQ, 256>>>(xp, ln1s + l * DM, ln1b + l * DM, nullptr, hh);

        mma_gemm<0, 0, 0, 0><<<g_qkvg, 256, DYNSM>>>(
            hh, wqkvh + (size_t)l * 3 * WA, wqkvl + (size_t)l * 3 * WA,
            nullptr, nullptr, qkvp, nullptr, DM, 3 * DM);

        split_qkv<<<SQ * DM / 1024, 256>>>(qkvp, qhp, khp, klp, vhp, vlp);

        attn_kernel<<<dim3(SQ / 16, NH), 128>>>(qhp, khp, klp, vhp, vlp, chp);

        mma_gemm<0, 0, 1, 0><<<g_1024, 256, DYNSM>>>(
            chp, woh + (size_t)l * WA, wol + (size_t)l * WA,
            nullptr, xp, xp, nullptr, DM, DM);

        ln_kernel<1><<<SQ, 256>>>(xp, ln2s + l * DM, ln2b + l * DM, nullptr, hh);

        mma_gemm<1, 1, 0, 1><<<g_4096, 256, DYNSM>>>(
            hh, w1h + (size_t)l * WM, w1l + (size_t)l * WM,
            b1 + l * MLPD, nullptr, nullptr, y1h, DM, MLPD);

        mma_gemm<1, 0, 1, 0><<<g_1024, 256, DYNSM>>>(
            y1h, w2h + (size_t)l * WM, w2l + (size_t)l * WM,
            b2 + l * DM, xp, xp, nullptr, MLPD, DM);
    }

    ln_kernel<0><<<SQ, 256>>>(xp, lnfs, lnfb, out, nullptr);
}